// round 14
// baseline (speedup 1.0000x reference)
#include <cuda_runtime.h>
#include <cuda_fp16.h>
#include <math.h>
#include <stdint.h>

#define B_   2
#define S_   2048
#define D_   2048
#define H_   16
#define HD_  128
#define MFF  8192
#define NR   (B_*S_)          // 4096 rows

// ---------------- scratch (static device globals; no allocation) ----------------
__device__ __half g_h    [(size_t)NR * D_];            // rmsnorm out (half)
__device__ __half g_qkvh [(size_t)NR * 3 * H_ * HD_];  // qkv (half)
__device__ __half g_vT   [(size_t)B_ * H_ * HD_ * S_]; // V transposed [b][h][d][s]
__device__ __half g_attn [(size_t)NR * D_];            // attention out (half)
__device__ float  g_x1   [(size_t)NR * D_];
__device__ float  g_gate [(size_t)NR * MFF];
__device__ float  g_up   [(size_t)NR * MFF];
__device__ __half g_gateh[(size_t)NR * MFF];
// half, transposed weights wT[n][k]
__device__ __half g_wqT[(size_t)(3 * H_ * HD_) * D_];
__device__ __half g_woT[(size_t)D_ * D_];
__device__ __half g_wgT[(size_t)MFF * D_];
__device__ __half g_wuT[(size_t)MFF * D_];
__device__ __half g_wdT[(size_t)D_ * MFF];

// ================= helpers =================
__device__ __forceinline__ uint32_t smem_u32(const void* p) {
    uint32_t a;
    asm("{ .reg .u64 t; cvta.to.shared.u64 t, %1; cvt.u32.u64 %0, t; }" : "=r"(a) : "l"(p));
    return a;
}
__device__ __forceinline__ void cp_async16(uint32_t dst, const void* src) {
    asm volatile("cp.async.cg.shared.global [%0], [%1], 16;" :: "r"(dst), "l"(src) : "memory");
}
__device__ __forceinline__ void mma_f16(float* c, const uint32_t* a, const uint32_t* b) {
    asm volatile(
        "mma.sync.aligned.m16n8k16.row.col.f32.f16.f16.f32 "
        "{%0,%1,%2,%3}, {%4,%5,%6,%7}, {%8,%9}, {%0,%1,%2,%3};"
        : "+f"(c[0]), "+f"(c[1]), "+f"(c[2]), "+f"(c[3])
        : "r"(a[0]), "r"(a[1]), "r"(a[2]), "r"(a[3]), "r"(b[0]), "r"(b[1]));
}

// ---------------- weight convert + transpose: fp32 [K][N] -> half [N][K] --------
__global__ void convT_kernel(const float* __restrict__ in, __half* __restrict__ out,
                             int K, int N) {
    __shared__ float tile[32][33];
    int n0 = blockIdx.x * 32, k0 = blockIdx.y * 32;
    int tx = threadIdx.x, ty = threadIdx.y;
    #pragma unroll
    for (int j = 0; j < 32; j += 8)
        tile[ty + j][tx] = in[(size_t)(k0 + ty + j) * N + n0 + tx];
    __syncthreads();
    #pragma unroll
    for (int j = 0; j < 32; j += 8)
        out[(size_t)(n0 + ty + j) * K + k0 + tx] = __float2half_rn(tile[tx][ty + j]);
}

// ---------------- V transpose: qkvh [b][s][3][H][HD] -> vT [b][h][d][s] ----------
__global__ void vT_kernel(const __half* __restrict__ qkvh, __half* __restrict__ out) {
    __shared__ float tile[32][33];
    int bh = blockIdx.z;
    int b = bh >> 4, h = bh & 15;
    int s0 = blockIdx.x * 32, d0 = blockIdx.y * 32;
    int tx = threadIdx.x, ty = threadIdx.y;
    #pragma unroll
    for (int j = 0; j < 32; j += 8)
        tile[ty + j][tx] = __half2float(
            qkvh[(((size_t)b * S_ + s0 + ty + j) * 3 * H_ + 2 * H_ + h) * HD_ + d0 + tx]);
    __syncthreads();
    #pragma unroll
    for (int j = 0; j < 32; j += 8)
        out[(((size_t)bh * HD_) + d0 + ty + j) * S_ + s0 + tx] =
            __float2half_rn(tile[tx][ty + j]);
}

// ================= fp16 mma.sync GEMM: C[M][N] = A[M][K] @ BT[N][K]^T (+epi) =====
// CTA tile 128x256, K-slab 64, double buffered. 512 threads = 16 warps 4(M)x4(N);
// warp tile 32x64 -> 2x8 m16n8k16 frags (acc 64 regs -> 4 warps/SMSP).
#define HST 72                         // halfs per row (64 data + 8 pad); 36w == 4 mod 32
#define A_STGH (128 * HST)             // 9216 halfs / stage
#define B_STGH (256 * HST)             // 18432 halfs / stage
#define B_BASEH (2 * A_STGH)
#define GEMM_SMEM ((2 * A_STGH + 2 * B_STGH) * 2)   // 110592 bytes

__device__ __forceinline__ void load_stage(
    uint32_t sb, const __half* Ag, const __half* Bg, int K,
    int t, int stage, int ks)
{
    uint32_t abase = sb + (uint32_t)(stage * A_STGH) * 2;
    uint32_t bbase = sb + (uint32_t)(B_BASEH + stage * B_STGH) * 2;
    #pragma unroll
    for (int i = 0; i < 2; i++) {              // A: 128 rows x 8 granules of 16B
        int idx = i * 512 + t;
        int r = idx >> 3, g = idx & 7;
        cp_async16(abase + (uint32_t)(r * HST + g * 8) * 2,
                   Ag + (size_t)r * K + ks + g * 8);
    }
    #pragma unroll
    for (int i = 0; i < 4; i++) {              // B: 256 rows x 8 granules of 16B
        int idx = i * 512 + t;
        int r = idx >> 3, g = idx & 7;
        cp_async16(bbase + (uint32_t)(r * HST + g * 8) * 2,
                   Bg + (size_t)r * K + ks + g * 8);
    }
    asm volatile("cp.async.commit_group;" ::: "memory");
}

// EPI: 0: fp32 C=A@B   1: fp32 C=A@B+Res   3: half C=A@B
template<int EPI>
__global__ void __launch_bounds__(512, 1)
gemm_mma_kernel(const __half* __restrict__ A, const __half* __restrict__ BT,
                const float* __restrict__ Res, float* __restrict__ C,
                int N, int K)
{
    extern __shared__ __half smh[];
    uint32_t sb = smem_u32(smh);

    int t   = threadIdx.x;
    int w   = t >> 5, lane = t & 31;
    int G   = lane >> 2, T = lane & 3;
    int wm  = w >> 2, wn = w & 3;            // warp grid 4(M) x 4(N)
    int bm  = blockIdx.y, bn = blockIdx.x;

    const __half* Ag = A  + (size_t)bm * 128 * K;
    const __half* Bg = BT + (size_t)bn * 256 * K;
    const int nsteps = K / 64;

    float acc[2][8][4];
    #pragma unroll
    for (int i = 0; i < 2; i++)
        #pragma unroll
        for (int j = 0; j < 8; j++)
            #pragma unroll
            for (int r = 0; r < 4; r++) acc[i][j][r] = 0.f;

    load_stage(sb, Ag, Bg, K, t, 0, 0);
    load_stage(sb, Ag, Bg, K, t, 1, 64);

    for (int it = 0; it < nsteps; it++) {
        int cur = it & 1;
        if (it == nsteps - 1) asm volatile("cp.async.wait_group 0;" ::: "memory");
        else                  asm volatile("cp.async.wait_group 1;" ::: "memory");
        __syncthreads();

        const __half* As = smh + cur * A_STGH;
        const __half* Bs = smh + B_BASEH + cur * B_STGH;

        #pragma unroll
        for (int kk = 0; kk < 4; kk++) {
            int kb = kk * 16;
            uint32_t af[2][4];
            #pragma unroll
            for (int i = 0; i < 2; i++) {
                int m0 = wm * 32 + i * 16 + G;
                const __half* ar0 = As + m0 * HST + kb + 2 * T;
                const __half* ar1 = As + (m0 + 8) * HST + kb + 2 * T;
                af[i][0] = *(const uint32_t*)(ar0);
                af[i][1] = *(const uint32_t*)(ar1);
                af[i][2] = *(const uint32_t*)(ar0 + 8);
                af[i][3] = *(const uint32_t*)(ar1 + 8);
            }
            uint32_t bf[8][2];
            #pragma unroll
            for (int j = 0; j < 8; j++) {
                int n0 = wn * 64 + j * 8 + G;
                const __half* br = Bs + n0 * HST + kb + 2 * T;
                bf[j][0] = *(const uint32_t*)(br);
                bf[j][1] = *(const uint32_t*)(br + 8);
            }
            #pragma unroll
            for (int i = 0; i < 2; i++)
                #pragma unroll
                for (int j = 0; j < 8; j++)
                    mma_f16(acc[i][j], af[i], bf[j]);
        }
        __syncthreads();
        if (it + 2 < nsteps)
            load_stage(sb, Ag, Bg, K, t, cur, (it + 2) * 64);
    }

    #pragma unroll
    for (int i = 0; i < 2; i++) {
        int row = bm * 128 + wm * 32 + i * 16 + G;
        #pragma unroll
        for (int j = 0; j < 8; j++) {
            int col = bn * 256 + wn * 64 + j * 8 + 2 * T;
            size_t o0 = (size_t)row * N + col;
            size_t o1 = (size_t)(row + 8) * N + col;
            float2 v0 = make_float2(acc[i][j][0], acc[i][j][1]);
            float2 v1 = make_float2(acc[i][j][2], acc[i][j][3]);
            if (EPI == 1) {
                float2 r0 = *(const float2*)(Res + o0);
                float2 r1 = *(const float2*)(Res + o1);
                v0.x += r0.x; v0.y += r0.y;
                v1.x += r1.x; v1.y += r1.y;
            }
            if (EPI == 3) {
                *(__half2*)((__half*)C + o0) = __floats2half2_rn(v0.x, v0.y);
                *(__half2*)((__half*)C + o1) = __floats2half2_rn(v1.x, v1.y);
            } else {
                *(float2*)(C + o0) = v0;
                *(float2*)(C + o1) = v1;
            }
        }
    }
}

// ================= fp16 tensor-core flash attention (causal) =================
#define ABR 128
#define ABC 64
#define QSTH 136    // Q/K row halfs: 68 words == 4 mod 32 -> banks 4G+T
#define VSTH 72     // V^T/P row halfs: 36 words == 4 mod 32
#define PSTH 72
#define KVH_STG (64 * QSTH + 128 * VSTH)               // 17920 halfs per stage
#define ATTN_SMEM ((2 * KVH_STG + ABR * PSTH) * 2)     // 90112 bytes

__device__ __forceinline__ void attn_load_kv(
    uint32_t sb, const __half* kbase, const __half* vtbase, int t, int stage, int k0)
{
    const size_t rs = (size_t)3 * H_ * HD_;
    uint32_t kdst = sb + (uint32_t)(stage * KVH_STG) * 2;
    uint32_t vdst = kdst + (uint32_t)(64 * QSTH) * 2;
    #pragma unroll
    for (int i = 0; i < 4; i++) {
        int idx = i * 256 + t;
        int r = idx >> 4, g = idx & 15;
        cp_async16(kdst + (uint32_t)(r * QSTH + g * 8) * 2,
                   kbase + (size_t)(k0 + r) * rs + g * 8);
    }
    #pragma unroll
    for (int i = 0; i < 4; i++) {
        int idx = i * 256 + t;
        int r = idx >> 3, g = idx & 7;
        cp_async16(vdst + (uint32_t)(r * VSTH + g * 8) * 2,
                   vtbase + (size_t)r * S_ + k0 + g * 8);
    }
    asm volatile("cp.async.commit_group;" ::: "memory");
}

__global__ void __launch_bounds__(256, 1)
attn_mma_kernel(const __half* __restrict__ qkvh, const __half* __restrict__ vT,
                __half* __restrict__ out) {
    extern __shared__ __half smh[];
    uint32_t sb = smem_u32(smh);
    int t = threadIdx.x, w = t >> 5, lane = t & 31;
    int G = lane >> 2, T = lane & 3;
    int qb = blockIdx.x, h = blockIdx.y, b = blockIdx.z;
    int q0 = qb * ABR;

    const size_t rs = (size_t)3 * H_ * HD_;
    const __half* qbase  = qkvh + (((size_t)b * S_ + q0) * 3 * H_ + h) * HD_;
    const __half* kbase  = qkvh + (((size_t)b * S_) * 3 * H_ + H_ + h) * HD_;
    const __half* vtbase = vT + ((size_t)(b * H_ + h) * HD_) * S_;
    const float scale = 0.08838834764831845f;   // 1/sqrt(128)

    // ---- Q tile (128 rows x 128 d, half) -> smem stage0 region ----
    #pragma unroll
    for (int i = 0; i < 8; i++) {
        int idx = i * 256 + t;
        int r = idx >> 4, g = idx & 15;
        cp_async16(sb + (uint32_t)(r * QSTH + g * 8) * 2,
                   qbase + (size_t)r * rs + g * 8);
    }
    asm volatile("cp.async.commit_group;" ::: "memory");
    asm volatile("cp.async.wait_group 0;" ::: "memory");
    __syncthreads();

    uint32_t qf[8][4];
    {
        int m0 = w * 16 + G;
        #pragma unroll
        for (int kk = 0; kk < 8; kk++) {
            const __half* ar0 = smh + m0 * QSTH + kk * 16 + 2 * T;
            const __half* ar1 = smh + (m0 + 8) * QSTH + kk * 16 + 2 * T;
            qf[kk][0] = *(const uint32_t*)(ar0);
            qf[kk][1] = *(const uint32_t*)(ar1);
            qf[kk][2] = *(const uint32_t*)(ar0 + 8);
            qf[kk][3] = *(const uint32_t*)(ar1 + 8);
        }
    }
    __syncthreads();

    __half* Ps = smh + 2 * KVH_STG;
    const int ntiles = 2 * qb + 2;
    const int qg0 = q0 + w * 16 + G;
    const int qg1 = qg0 + 8;

    float o[16][4];
    #pragma unroll
    for (int j = 0; j < 16; j++)
        #pragma unroll
        for (int r = 0; r < 4; r++) o[j][r] = 0.f;
    float m0r = -INFINITY, m1r = -INFINITY, l0r = 0.f, l1r = 0.f;

    attn_load_kv(sb, kbase, vtbase, t, 0, 0);
    attn_load_kv(sb, kbase, vtbase, t, 1, ABC);

    for (int kt = 0; kt < ntiles; kt++) {
        int cur = kt & 1;
        if (kt == ntiles - 1) asm volatile("cp.async.wait_group 0;" ::: "memory");
        else                  asm volatile("cp.async.wait_group 1;" ::: "memory");
        __syncthreads();

        const __half* Ks = smh + cur * KVH_STG;
        const __half* Vs = Ks + 64 * QSTH;
        int k0 = kt * ABC;

        // ---- S = Q K^T ----
        float s[8][4];
        #pragma unroll
        for (int j = 0; j < 8; j++)
            #pragma unroll
            for (int r = 0; r < 4; r++) s[j][r] = 0.f;

        #pragma unroll
        for (int kk = 0; kk < 8; kk++) {
            int kb = kk * 16;
            #pragma unroll
            for (int j = 0; j < 8; j++) {
                const __half* br = Ks + (j * 8 + G) * QSTH + kb + 2 * T;
                uint32_t bf[2];
                bf[0] = *(const uint32_t*)(br);
                bf[1] = *(const uint32_t*)(br + 8);
                mma_f16(s[j], qf[kk], bf);
            }
        }

        // ---- online softmax ----
        bool domask = (kt >= 2 * qb);
        float mx0 = -INFINITY, mx1 = -INFINITY;
        #pragma unroll
        for (int j = 0; j < 8; j++) {
            s[j][0] *= scale; s[j][1] *= scale; s[j][2] *= scale; s[j][3] *= scale;
            if (domask) {
                int kv = k0 + j * 8 + 2 * T;
                if (kv     > qg0) s[j][0] = -INFINITY;
                if (kv + 1 > qg0) s[j][1] = -INFINITY;
                if (kv     > qg1) s[j][2] = -INFINITY;
                if (kv + 1 > qg1) s[j][3] = -INFINITY;
            }
            mx0 = fmaxf(mx0, fmaxf(s[j][0], s[j][1]));
            mx1 = fmaxf(mx1, fmaxf(s[j][2], s[j][3]));
        }
        mx0 = fmaxf(mx0, __shfl_xor_sync(0xffffffffu, mx0, 1));
        mx0 = fmaxf(mx0, __shfl_xor_sync(0xffffffffu, mx0, 2));
        mx1 = fmaxf(mx1, __shfl_xor_sync(0xffffffffu, mx1, 1));
        mx1 = fmaxf(mx1, __shfl_xor_sync(0xffffffffu, mx1, 2));

        float mn0 = fmaxf(m0r, mx0), mn1 = fmaxf(m1r, mx1);
        float a0 = __expf(m0r - mn0), a1 = __expf(m1r - mn1);
        m0r = mn0; m1r = mn1;

        __syncwarp();
        float rs0 = 0.f, rs1 = 0.f;
        #pragma unroll
        for (int j = 0; j < 8; j++) {
            float p0 = __expf(s[j][0] - mn0);
            float p1 = __expf(s[j][1] - mn0);
            float p2 = __expf(s[j][2] - mn1);
            float p3 = __expf(s[j][3] - mn1);
            rs0 += p0 + p1; rs1 += p2 + p3;
            int c = j * 8 + 2 * T;
            *(__half2*)(&Ps[(w * 16 + G    ) * PSTH + c]) = __floats2half2_rn(p0, p1);
            *(__half2*)(&Ps[(w * 16 + G + 8) * PSTH + c]) = __floats2half2_rn(p2, p3);
        }
        rs0 += __shfl_xor_sync(0xffffffffu, rs0, 1);
        rs0 += __shfl_xor_sync(0xffffffffu, rs0, 2);
        rs1 += __shfl_xor_sync(0xffffffffu, rs1, 1);
        rs1 += __shfl_xor_sync(0xffffffffu, rs1, 2);
        l0r = l0r * a0 + rs0;
        l1r = l1r * a1 + rs1;

        #pragma unroll
        for (int j = 0; j < 16; j++) {
            o[j][0] *= a0; o[j][1] *= a0;
            o[j][2] *= a1; o[j][3] *= a1;
        }
        __syncwarp();

        // ---- O += P @ V ----
        #pragma unroll
        for (int kc = 0; kc < 4; kc++) {
            int kb = kc * 16;
            const __half* pr0 = Ps + (w * 16 + G) * PSTH + kb + 2 * T;
            const __half* pr1 = Ps + (w * 16 + G + 8) * PSTH + kb + 2 * T;
            uint32_t af[4];
            af[0] = *(const uint32_t*)(pr0);
            af[1] = *(const uint32_t*)(pr1);
            af[2] = *(const uint32_t*)(pr0 + 8);
            af[3] = *(const uint32_t*)(pr1 + 8);
            #pragma unroll
            for (int j = 0; j < 16; j++) {
                const __half* br = Vs + (j * 8 + G) * VSTH + kb + 2 * T;
                uint32_t bf[2];
                bf[0] = *(const uint32_t*)(br);
                bf[1] = *(const uint32_t*)(br + 8);
                mma_f16(o[j], af, bf);
            }
        }
        __syncthreads();
        if (kt + 2 < ntiles)
            attn_load_kv(sb, kbase, vtbase, t, cur, (kt + 2) * ABC);
    }

    // ---- write O / l as half ----
    float i0 = 1.0f / l0r, i1 = 1.0f / l1r;
    #pragma unroll
    for (int j = 0; j < 16; j++) {
        int col = h * HD_ + j * 8 + 2 * T;
        size_t o0 = ((size_t)b * S_ + qg0) * D_ + col;
        size_t o1 = ((size_t)b * S_ + qg1) * D_ + col;
        *(__half2*)(out + o0) = __floats2half2_rn(o[j][0] * i0, o[j][1] * i0);
        *(__half2*)(out + o1) = __floats2half2_rn(o[j][2] * i1, o[j][3] * i1);
    }
}

// ---------------- RMSNorm (writes half) ----------------
__global__ void rmsnorm_kernel(const float* __restrict__ x,
                               const float* __restrict__ sc,
                               __half* __restrict__ o) {
    int row = blockIdx.x;
    const float4* xr  = (const float4*)(x + (size_t)row * D_);
    __half2* orow     = (__half2*)(o + (size_t)row * D_);
    const float4* sc4 = (const float4*)sc;
    int t = threadIdx.x;

    float4 v0 = xr[t];
    float4 v1 = xr[t + 256];
    float ss = v0.x*v0.x + v0.y*v0.y + v0.z*v0.z + v0.w*v0.w
             + v1.x*v1.x + v1.y*v1.y + v1.z*v1.z + v1.w*v1.w;
    #pragma unroll
    for (int off = 16; off > 0; off >>= 1)
        ss += __shfl_xor_sync(0xffffffffu, ss, off);

    __shared__ float red[8];
    __shared__ float s_inv;
    if ((t & 31) == 0) red[t >> 5] = ss;
    __syncthreads();
    if (t == 0) {
        float tot = 0.f;
        #pragma unroll
        for (int i = 0; i < 8; i++) tot += red[i];
        s_inv = rsqrtf(tot * (1.0f / (float)D_) + 1e-6f);
    }
    __syncthreads();
    float inv = s_inv;

    float4 s0 = sc4[t], s1 = sc4[t + 256];
    orow[2*t]           = __floats2half2_rn(v0.x * inv * s0.x, v0.y * inv * s0.y);
    orow[2*t + 1]       = __floats2half2_rn(v0.z * inv * s0.z, v0.w * inv * s0.w);
    orow[2*(t+256)]     = __floats2half2_rn(v1.x * inv * s1.x, v1.y * inv * s1.y);
    orow[2*(t+256) + 1] = __floats2half2_rn(v1.z * inv * s1.z, v1.w * inv * s1.w);
}

// ---------------- silu(gate) * up -> half ----------------
__global__ void silu_mul_kernel(const float* __restrict__ g, const float* __restrict__ u,
                                __half* __restrict__ out) {
    size_t i = (size_t)blockIdx.x * blockDim.x + threadIdx.x;
    float4 gv = ((const float4*)g)[i];
    float4 uv = ((const float4*)u)[i];
    float r0 = gv.x / (1.f + __expf(-gv.x)) * uv.x;
    float r1 = gv.y / (1.f + __expf(-gv.y)) * uv.y;
    float r2 = gv.z / (1.f + __expf(-gv.z)) * uv.z;
    float r3 = gv.w / (1.f + __expf(-gv.w)) * uv.w;
    ((__half2*)out)[2*i]     = __floats2half2_rn(r0, r1);
    ((__half2*)out)[2*i + 1] = __floats2half2_rn(r2, r3);
}

// ---------------- launch ----------------
extern "C" void kernel_launch(void* const* d_in, const int* in_sizes, int n_in,
                              void* d_out, int out_size) {
    (void)in_sizes; (void)n_in; (void)out_size;
    const float* x      = (const float*)d_in[0];
    const float* w_qkv  = (const float*)d_in[1];
    const float* w_o    = (const float*)d_in[2];
    const float* w_gate = (const float*)d_in[3];
    const float* w_up   = (const float*)d_in[4];
    const float* w_down = (const float*)d_in[5];
    const float* rms1   = (const float*)d_in[6];
    const float* rms2   = (const float*)d_in[7];
    float* out = (float*)d_out;

    __half *h, *qkvh, *vT, *attn, *gateh, *wq, *wo, *wg, *wu, *wd;
    float *x1, *gate, *up;
    cudaGetSymbolAddress((void**)&h,     g_h);
    cudaGetSymbolAddress((void**)&qkvh,  g_qkvh);
    cudaGetSymbolAddress((void**)&vT,    g_vT);
    cudaGetSymbolAddress((void**)&attn,  g_attn);
    cudaGetSymbolAddress((void**)&x1,    g_x1);
    cudaGetSymbolAddress((void**)&gate,  g_gate);
    cudaGetSymbolAddress((void**)&up,    g_up);
    cudaGetSymbolAddress((void**)&gateh, g_gateh);
    cudaGetSymbolAddress((void**)&wq,    g_wqT);
    cudaGetSymbolAddress((void**)&wo,    g_woT);
    cudaGetSymbolAddress((void**)&wg,    g_wgT);
    cudaGetSymbolAddress((void**)&wu,    g_wuT);
    cudaGetSymbolAddress((void**)&wd,    g_wdT);

    cudaFuncSetAttribute(attn_mma_kernel,
                         cudaFuncAttributeMaxDynamicSharedMemorySize, ATTN_SMEM);
    cudaFuncSetAttribute(gemm_mma_kernel<0>,
                         cudaFuncAttributeMaxDynamicSharedMemorySize, GEMM_SMEM);
    cudaFuncSetAttribute(gemm_mma_kernel<1>,
                         cudaFuncAttributeMaxDynamicSharedMemorySize, GEMM_SMEM);
    cudaFuncSetAttribute(gemm_mma_kernel<3>,
                         cudaFuncAttributeMaxDynamicSharedMemorySize, GEMM_SMEM);

    dim3 tb(32, 8);
    convT_kernel<<<dim3((3*H_*HD_)/32, D_/32), tb>>>(w_qkv, wq, D_, 3*H_*HD_);  // 1
    convT_kernel<<<dim3(D_/32, D_/32), tb>>>(w_o, wo, D_, D_);                  // 2
    rmsnorm_kernel<<<NR, 256>>>(x, rms1, h);                                    // 3
    gemm_mma_kernel<3><<<dim3((3*H_*HD_)/256, NR/128), 512, GEMM_SMEM>>>(
        h, wq, nullptr, (float*)qkvh, 3*H_*HD_, D_);                            // 4
    vT_kernel<<<dim3(S_/32, HD_/32, B_*H_), dim3(32, 8)>>>(qkvh, vT);           // 5
    attn_mma_kernel<<<dim3(S_/ABR, H_, B_), 256, ATTN_SMEM>>>(qkvh, vT, attn);  // 6
    gemm_mma_kernel<1><<<dim3(D_/256, NR/128), 512, GEMM_SMEM>>>(
        attn, wo, x, x1, D_, D_);                                               // 7
    rmsnorm_kernel<<<NR, 256>>>(x1, rms2, h);                                   // 8
    convT_kernel<<<dim3(MFF/32, D_/32), tb>>>(w_gate, wg, D_, MFF);             // 9
    convT_kernel<<<dim3(MFF/32, D_/32), tb>>>(w_up,   wu, D_, MFF);             // 10
    convT_kernel<<<dim3(D_/32, MFF/32), tb>>>(w_down, wd, MFF, D_);             // 11
    gemm_mma_kernel<0><<<dim3(MFF/256, NR/128), 512, GEMM_SMEM>>>(
        h, wg, nullptr, gate, MFF, D_);                                         // 12
    gemm_mma_kernel<0><<<dim3(MFF/256, NR/128), 512, GEMM_SMEM>>>(
        h, wu, nullptr, up, MFF, D_);                                           // 13
    silu_mul_kernel<<<(unsigned)((size_t)NR * MFF / 4 / 256), 256>>>(gate, up, gateh); // 14
    gemm_mma_kernel<1><<<dim3(D_/256, NR/128), 512, GEMM_SMEM>>>(
        gateh, wd, x1, out, D_, MFF);                                           // 15
}

// round 15
// speedup vs baseline: 1.0477x; 1.0477x over previous
#include <cuda_runtime.h>
#include <cuda_fp16.h>
#include <math.h>
#include <stdint.h>

#define B_   2
#define S_   2048
#define D_   2048
#define H_   16
#define HD_  128
#define MFF  8192
#define NR   (B_*S_)          // 4096 rows

// ---------------- scratch (static device globals; no allocation) ----------------
__device__ __half g_h    [(size_t)NR * D_];            // rmsnorm out (half)
__device__ __half g_qkvh [(size_t)NR * 3 * H_ * HD_];  // qkv (half)
__device__ __half g_vT   [(size_t)B_ * H_ * HD_ * S_]; // V transposed [b][h][d][s]
__device__ __half g_attn [(size_t)NR * D_];            // attention out (half)
__device__ float  g_x1   [(size_t)NR * D_];
__device__ float  g_gate [(size_t)NR * MFF];
__device__ float  g_up   [(size_t)NR * MFF];
__device__ __half g_gateh[(size_t)NR * MFF];
// half, transposed weights wT[n][k]
__device__ __half g_wqT[(size_t)(3 * H_ * HD_) * D_];
__device__ __half g_woT[(size_t)D_ * D_];
__device__ __half g_wgT[(size_t)MFF * D_];
__device__ __half g_wuT[(size_t)MFF * D_];
__device__ __half g_wdT[(size_t)D_ * MFF];

// ================= helpers =================
__device__ __forceinline__ uint32_t smem_u32(const void* p) {
    uint32_t a;
    asm("{ .reg .u64 t; cvta.to.shared.u64 t, %1; cvt.u32.u64 %0, t; }" : "=r"(a) : "l"(p));
    return a;
}
__device__ __forceinline__ void cp_async16(uint32_t dst, const void* src) {
    asm volatile("cp.async.cg.shared.global [%0], [%1], 16;" :: "r"(dst), "l"(src) : "memory");
}
__device__ __forceinline__ void mma_f16(float* c, const uint32_t* a, const uint32_t* b) {
    asm volatile(
        "mma.sync.aligned.m16n8k16.row.col.f32.f16.f16.f32 "
        "{%0,%1,%2,%3}, {%4,%5,%6,%7}, {%8,%9}, {%0,%1,%2,%3};"
        : "+f"(c[0]), "+f"(c[1]), "+f"(c[2]), "+f"(c[3])
        : "r"(a[0]), "r"(a[1]), "r"(a[2]), "r"(a[3]), "r"(b[0]), "r"(b[1]));
}
__device__ __forceinline__ void ldsm4(uint32_t* r, uint32_t addr) {
    asm volatile("ldmatrix.sync.aligned.m8n8.x4.shared.b16 {%0,%1,%2,%3}, [%4];"
        : "=r"(r[0]), "=r"(r[1]), "=r"(r[2]), "=r"(r[3]) : "r"(addr));
}

// ---------------- weight convert + transpose: fp32 [K][N] -> half [N][K] --------
__global__ void convT_kernel(const float* __restrict__ in, __half* __restrict__ out,
                             int K, int N) {
    __shared__ float tile[32][33];
    int n0 = blockIdx.x * 32, k0 = blockIdx.y * 32;
    int tx = threadIdx.x, ty = threadIdx.y;
    #pragma unroll
    for (int j = 0; j < 32; j += 8)
        tile[ty + j][tx] = in[(size_t)(k0 + ty + j) * N + n0 + tx];
    __syncthreads();
    #pragma unroll
    for (int j = 0; j < 32; j += 8)
        out[(size_t)(n0 + ty + j) * K + k0 + tx] = __float2half_rn(tile[tx][ty + j]);
}

// ---------------- V transpose: qkvh [b][s][3][H][HD] -> vT [b][h][d][s] ----------
__global__ void vT_kernel(const __half* __restrict__ qkvh, __half* __restrict__ out) {
    __shared__ float tile[32][33];
    int bh = blockIdx.z;
    int b = bh >> 4, h = bh & 15;
    int s0 = blockIdx.x * 32, d0 = blockIdx.y * 32;
    int tx = threadIdx.x, ty = threadIdx.y;
    #pragma unroll
    for (int j = 0; j < 32; j += 8)
        tile[ty + j][tx] = __half2float(
            qkvh[(((size_t)b * S_ + s0 + ty + j) * 3 * H_ + 2 * H_ + h) * HD_ + d0 + tx]);
    __syncthreads();
    #pragma unroll
    for (int j = 0; j < 32; j += 8)
        out[(((size_t)bh * HD_) + d0 + ty + j) * S_ + s0 + tx] =
            __float2half_rn(tile[tx][ty + j]);
}

// ================= fp16 mma.sync GEMM: C[M][N] = A[M][K] @ BT[N][K]^T (+epi) =====
// CTA tile 128x256, K-slab 64, double buffered. 256 threads = 8 warps 2(M)x4(N);
// warp tile 64x64 -> 4x8 m16n8k16 frags. Fragment loads via ldmatrix.x4.
#define HST 72                         // halfs per row (64 data + 8 pad); 36w == 4 mod 32
#define A_STGH (128 * HST)             // 9216 halfs / stage
#define B_STGH (256 * HST)             // 18432 halfs / stage
#define B_BASEH (2 * A_STGH)
#define GEMM_SMEM ((2 * A_STGH + 2 * B_STGH) * 2)   // 110592 bytes

__device__ __forceinline__ void load_stage(
    uint32_t sb, const __half* Ag, const __half* Bg, int K,
    int t, int stage, int ks)
{
    uint32_t abase = sb + (uint32_t)(stage * A_STGH) * 2;
    uint32_t bbase = sb + (uint32_t)(B_BASEH + stage * B_STGH) * 2;
    #pragma unroll
    for (int i = 0; i < 4; i++) {              // A: 128 rows x 8 granules of 16B
        int idx = i * 256 + t;
        int r = idx >> 3, g = idx & 7;
        cp_async16(abase + (uint32_t)(r * HST + g * 8) * 2,
                   Ag + (size_t)r * K + ks + g * 8);
    }
    #pragma unroll
    for (int i = 0; i < 8; i++) {              // B: 256 rows x 8 granules of 16B
        int idx = i * 256 + t;
        int r = idx >> 3, g = idx & 7;
        cp_async16(bbase + (uint32_t)(r * HST + g * 8) * 2,
                   Bg + (size_t)r * K + ks + g * 8);
    }
    asm volatile("cp.async.commit_group;" ::: "memory");
}

// EPI: 0: fp32 C=A@B   1: fp32 C=A@B+Res   3: half C=A@B
template<int EPI>
__global__ void __launch_bounds__(256, 1)
gemm_mma_kernel(const __half* __restrict__ A, const __half* __restrict__ BT,
                const float* __restrict__ Res, float* __restrict__ C,
                int N, int K)
{
    extern __shared__ __half smh[];
    uint32_t sb = smem_u32(smh);

    int t   = threadIdx.x;
    int w   = t >> 5, lane = t & 31;
    int G   = lane >> 2, T = lane & 3;
    int wm  = w >> 2, wn = w & 3;            // warp grid 2(M) x 4(N)
    int bm  = blockIdx.y, bn = blockIdx.x;

    const __half* Ag = A  + (size_t)bm * 128 * K;
    const __half* Bg = BT + (size_t)bn * 256 * K;
    const int nsteps = K / 64;

    // ldmatrix per-thread address offsets (in halfs, before *2 for bytes)
    // A: matrices {a0,a1,a2,a3} = rows m0+(lane&15), col (lane>>4)*8
    const uint32_t a_off = (uint32_t)(((wm * 64 + (lane & 15)) * HST
                                       + ((lane >> 4) << 3)) * 2);
    // B: matrices {bf[j][0], bf[j][1], bf[j+1][0], bf[j+1][1]}
    const uint32_t b_off = (uint32_t)(((wn * 64 + ((lane >> 4) << 3) + (lane & 7)) * HST
                                       + (((lane >> 3) & 1) << 3)) * 2);

    float acc[4][8][4];
    #pragma unroll
    for (int i = 0; i < 4; i++)
        #pragma unroll
        for (int j = 0; j < 8; j++)
            #pragma unroll
            for (int r = 0; r < 4; r++) acc[i][j][r] = 0.f;

    load_stage(sb, Ag, Bg, K, t, 0, 0);
    load_stage(sb, Ag, Bg, K, t, 1, 64);

    for (int it = 0; it < nsteps; it++) {
        int cur = it & 1;
        if (it == nsteps - 1) asm volatile("cp.async.wait_group 0;" ::: "memory");
        else                  asm volatile("cp.async.wait_group 1;" ::: "memory");
        __syncthreads();

        uint32_t abase = sb + (uint32_t)(cur * A_STGH) * 2 + a_off;
        uint32_t bbase = sb + (uint32_t)((B_BASEH + cur * B_STGH)) * 2 + b_off;

        #pragma unroll
        for (int kk = 0; kk < 4; kk++) {
            uint32_t kbb = (uint32_t)(kk * 16 * 2);   // byte offset for this K-16 step
            uint32_t af[4][4];
            #pragma unroll
            for (int i = 0; i < 4; i++)
                ldsm4(af[i], abase + (uint32_t)(i * 16 * HST) * 2 + kbb);
            uint32_t bf[8][2];
            #pragma unroll
            for (int jj = 0; jj < 4; jj++) {
                uint32_t r[4];
                ldsm4(r, bbase + (uint32_t)(jj * 16 * HST) * 2 + kbb);
                bf[2 * jj    ][0] = r[0]; bf[2 * jj    ][1] = r[1];
                bf[2 * jj + 1][0] = r[2]; bf[2 * jj + 1][1] = r[3];
            }
            #pragma unroll
            for (int i = 0; i < 4; i++)
                #pragma unroll
                for (int j = 0; j < 8; j++)
                    mma_f16(acc[i][j], af[i], bf[j]);
        }
        __syncthreads();
        if (it + 2 < nsteps)
            load_stage(sb, Ag, Bg, K, t, cur, (it + 2) * 64);
    }

    #pragma unroll
    for (int i = 0; i < 4; i++) {
        int row = bm * 128 + wm * 64 + i * 16 + G;
        #pragma unroll
        for (int j = 0; j < 8; j++) {
            int col = bn * 256 + wn * 64 + j * 8 + 2 * T;
            size_t o0 = (size_t)row * N + col;
            size_t o1 = (size_t)(row + 8) * N + col;
            float2 v0 = make_float2(acc[i][j][0], acc[i][j][1]);
            float2 v1 = make_float2(acc[i][j][2], acc[i][j][3]);
            if (EPI == 1) {
                float2 r0 = *(const float2*)(Res + o0);
                float2 r1 = *(const float2*)(Res + o1);
                v0.x += r0.x; v0.y += r0.y;
                v1.x += r1.x; v1.y += r1.y;
            }
            if (EPI == 3) {
                *(__half2*)((__half*)C + o0) = __floats2half2_rn(v0.x, v0.y);
                *(__half2*)((__half*)C + o1) = __floats2half2_rn(v1.x, v1.y);
            } else {
                *(float2*)(C + o0) = v0;
                *(float2*)(C + o1) = v1;
            }
        }
    }
}

// ================= fp16 tensor-core flash attention (causal) =================
#define ABR 128
#define ABC 64
#define QSTH 136    // Q/K row halfs: 68 words == 4 mod 32 -> banks 4G+T
#define VSTH 72     // V^T/P row halfs: 36 words == 4 mod 32
#define PSTH 72
#define KVH_STG (64 * QSTH + 128 * VSTH)               // 17920 halfs per stage
#define ATTN_SMEM ((2 * KVH_STG + ABR * PSTH) * 2)     // 90112 bytes

__device__ __forceinline__ void attn_load_kv(
    uint32_t sb, const __half* kbase, const __half* vtbase, int t, int stage, int k0)
{
    const size_t rs = (size_t)3 * H_ * HD_;
    uint32_t kdst = sb + (uint32_t)(stage * KVH_STG) * 2;
    uint32_t vdst = kdst + (uint32_t)(64 * QSTH) * 2;
    #pragma unroll
    for (int i = 0; i < 4; i++) {
        int idx = i * 256 + t;
        int r = idx >> 4, g = idx & 15;
        cp_async16(kdst + (uint32_t)(r * QSTH + g * 8) * 2,
                   kbase + (size_t)(k0 + r) * rs + g * 8);
    }
    #pragma unroll
    for (int i = 0; i < 4; i++) {
        int idx = i * 256 + t;
        int r = idx >> 3, g = idx & 7;
        cp_async16(vdst + (uint32_t)(r * VSTH + g * 8) * 2,
                   vtbase + (size_t)r * S_ + k0 + g * 8);
    }
    asm volatile("cp.async.commit_group;" ::: "memory");
}

__global__ void __launch_bounds__(256, 1)
attn_mma_kernel(const __half* __restrict__ qkvh, const __half* __restrict__ vT,
                __half* __restrict__ out) {
    extern __shared__ __half smh[];
    uint32_t sb = smem_u32(smh);
    int t = threadIdx.x, w = t >> 5, lane = t & 31;
    int G = lane >> 2, T = lane & 3;
    int qb = blockIdx.x, h = blockIdx.y, b = blockIdx.z;
    int q0 = qb * ABR;

    const size_t rs = (size_t)3 * H_ * HD_;
    const __half* qbase  = qkvh + (((size_t)b * S_ + q0) * 3 * H_ + h) * HD_;
    const __half* kbase  = qkvh + (((size_t)b * S_) * 3 * H_ + H_ + h) * HD_;
    const __half* vtbase = vT + ((size_t)(b * H_ + h) * HD_) * S_;
    const float scale = 0.08838834764831845f;   // 1/sqrt(128)

    // ---- Q tile (128 rows x 128 d, half) -> smem stage0 region ----
    #pragma unroll
    for (int i = 0; i < 8; i++) {
        int idx = i * 256 + t;
        int r = idx >> 4, g = idx & 15;
        cp_async16(sb + (uint32_t)(r * QSTH + g * 8) * 2,
                   qbase + (size_t)r * rs + g * 8);
    }
    asm volatile("cp.async.commit_group;" ::: "memory");
    asm volatile("cp.async.wait_group 0;" ::: "memory");
    __syncthreads();

    uint32_t qf[8][4];
    {
        int m0 = w * 16 + G;
        #pragma unroll
        for (int kk = 0; kk < 8; kk++) {
            const __half* ar0 = smh + m0 * QSTH + kk * 16 + 2 * T;
            const __half* ar1 = smh + (m0 + 8) * QSTH + kk * 16 + 2 * T;
            qf[kk][0] = *(const uint32_t*)(ar0);
            qf[kk][1] = *(const uint32_t*)(ar1);
            qf[kk][2] = *(const uint32_t*)(ar0 + 8);
            qf[kk][3] = *(const uint32_t*)(ar1 + 8);
        }
    }
    __syncthreads();

    __half* Ps = smh + 2 * KVH_STG;
    const int ntiles = 2 * qb + 2;
    const int qg0 = q0 + w * 16 + G;
    const int qg1 = qg0 + 8;

    float o[16][4];
    #pragma unroll
    for (int j = 0; j < 16; j++)
        #pragma unroll
        for (int r = 0; r < 4; r++) o[j][r] = 0.f;
    float m0r = -INFINITY, m1r = -INFINITY, l0r = 0.f, l1r = 0.f;

    attn_load_kv(sb, kbase, vtbase, t, 0, 0);
    attn_load_kv(sb, kbase, vtbase, t, 1, ABC);

    for (int kt = 0; kt < ntiles; kt++) {
        int cur = kt & 1;
        if (kt == ntiles - 1) asm volatile("cp.async.wait_group 0;" ::: "memory");
        else                  asm volatile("cp.async.wait_group 1;" ::: "memory");
        __syncthreads();

        const __half* Ks = smh + cur * KVH_STG;
        const __half* Vs = Ks + 64 * QSTH;
        int k0 = kt * ABC;

        // ---- S = Q K^T ----
        float s[8][4];
        #pragma unroll
        for (int j = 0; j < 8; j++)
            #pragma unroll
            for (int r = 0; r < 4; r++) s[j][r] = 0.f;

        #pragma unroll
        for (int kk = 0; kk < 8; kk++) {
            int kb = kk * 16;
            #pragma unroll
            for (int j = 0; j < 8; j++) {
                const __half* br = Ks + (j * 8 + G) * QSTH + kb + 2 * T;
                uint32_t bf[2];
                bf[0] = *(const uint32_t*)(br);
                bf[1] = *(const uint32_t*)(br + 8);
                mma_f16(s[j], qf[kk], bf);
            }
        }

        // ---- online softmax ----
        bool domask = (kt >= 2 * qb);
        float mx0 = -INFINITY, mx1 = -INFINITY;
        #pragma unroll
        for (int j = 0; j < 8; j++) {
            s[j][0] *= scale; s[j][1] *= scale; s[j][2] *= scale; s[j][3] *= scale;
            if (domask) {
                int kv = k0 + j * 8 + 2 * T;
                if (kv     > qg0) s[j][0] = -INFINITY;
                if (kv + 1 > qg0) s[j][1] = -INFINITY;
                if (kv     > qg1) s[j][2] = -INFINITY;
                if (kv + 1 > qg1) s[j][3] = -INFINITY;
            }
            mx0 = fmaxf(mx0, fmaxf(s[j][0], s[j][1]));
            mx1 = fmaxf(mx1, fmaxf(s[j][2], s[j][3]));
        }
        mx0 = fmaxf(mx0, __shfl_xor_sync(0xffffffffu, mx0, 1));
        mx0 = fmaxf(mx0, __shfl_xor_sync(0xffffffffu, mx0, 2));
        mx1 = fmaxf(mx1, __shfl_xor_sync(0xffffffffu, mx1, 1));
        mx1 = fmaxf(mx1, __shfl_xor_sync(0xffffffffu, mx1, 2));

        float mn0 = fmaxf(m0r, mx0), mn1 = fmaxf(m1r, mx1);
        float a0 = __expf(m0r - mn0), a1 = __expf(m1r - mn1);
        m0r = mn0; m1r = mn1;

        __syncwarp();
        float rs0 = 0.f, rs1 = 0.f;
        #pragma unroll
        for (int j = 0; j < 8; j++) {
            float p0 = __expf(s[j][0] - mn0);
            float p1 = __expf(s[j][1] - mn0);
            float p2 = __expf(s[j][2] - mn1);
            float p3 = __expf(s[j][3] - mn1);
            rs0 += p0 + p1; rs1 += p2 + p3;
            int c = j * 8 + 2 * T;
            *(__half2*)(&Ps[(w * 16 + G    ) * PSTH + c]) = __floats2half2_rn(p0, p1);
            *(__half2*)(&Ps[(w * 16 + G + 8) * PSTH + c]) = __floats2half2_rn(p2, p3);
        }
        rs0 += __shfl_xor_sync(0xffffffffu, rs0, 1);
        rs0 += __shfl_xor_sync(0xffffffffu, rs0, 2);
        rs1 += __shfl_xor_sync(0xffffffffu, rs1, 1);
        rs1 += __shfl_xor_sync(0xffffffffu, rs1, 2);
        l0r = l0r * a0 + rs0;
        l1r = l1r * a1 + rs1;

        #pragma unroll
        for (int j = 0; j < 16; j++) {
            o[j][0] *= a0; o[j][1] *= a0;
            o[j][2] *= a1; o[j][3] *= a1;
        }
        __syncwarp();

        // ---- O += P @ V ----
        #pragma unroll
        for (int kc = 0; kc < 4; kc++) {
            int kb = kc * 16;
            const __half* pr0 = Ps + (w * 16 + G) * PSTH + kb + 2 * T;
            const __half* pr1 = Ps + (w * 16 + G + 8) * PSTH + kb + 2 * T;
            uint32_t af[4];
            af[0] = *(const uint32_t*)(pr0);
            af[1] = *(const uint32_t*)(pr1);
            af[2] = *(const uint32_t*)(pr0 + 8);
            af[3] = *(const uint32_t*)(pr1 + 8);
            #pragma unroll
            for (int j = 0; j < 16; j++) {
                const __half* br = Vs + (j * 8 + G) * VSTH + kb + 2 * T;
                uint32_t bf[2];
                bf[0] = *(const uint32_t*)(br);
                bf[1] = *(const uint32_t*)(br + 8);
                mma_f16(o[j], af, bf);
            }
        }
        __syncthreads();
        if (kt + 2 < ntiles)
            attn_load_kv(sb, kbase, vtbase, t, cur, (kt + 2) * ABC);
    }

    // ---- write O / l as half ----
    float i0 = 1.0f / l0r, i1 = 1.0f / l1r;
    #pragma unroll
    for (int j = 0; j < 16; j++) {
        int col = h * HD_ + j * 8 + 2 * T;
        size_t o0 = ((size_t)b * S_ + qg0) * D_ + col;
        size_t o1 = ((size_t)b * S_ + qg1) * D_ + col;
        *(__half2*)(out + o0) = __floats2half2_rn(o[j][0] * i0, o[j][1] * i0);
        *(__half2*)(out + o1) = __floats2half2_rn(o[j][2] * i1, o[j][3] * i1);
    }
}

// ---------------- RMSNorm (writes half) ----------------
__global__ void rmsnorm_kernel(const float* __restrict__ x,
                               const float* __restrict__ sc,
                               __half* __restrict__ o) {
    int row = blockIdx.x;
    const float4* xr  = (const float4*)(x + (size_t)row * D_);
    __half2* orow     = (__half2*)(o + (size_t)row * D_);
    const float4* sc4 = (const float4*)sc;
    int t = threadIdx.x;

    float4 v0 = xr[t];
    float4 v1 = xr[t + 256];
    float ss = v0.x*v0.x + v0.y*v0.y + v0.z*v0.z + v0.w*v0.w
             + v1.x*v1.x + v1.y*v1.y + v1.z*v1.z + v1.w*v1.w;
    #pragma unroll
    for (int off = 16; off > 0; off >>= 1)
        ss += __shfl_xor_sync(0xffffffffu, ss, off);

    __shared__ float red[8];
    __shared__ float s_inv;
    if ((t & 31) == 0) red[t >> 5] = ss;
    __syncthreads();
    if (t == 0) {
        float tot = 0.f;
        #pragma unroll
        for (int i = 0; i < 8; i++) tot += red[i];
        s_inv = rsqrtf(tot * (1.0f / (float)D_) + 1e-6f);
    }
    __syncthreads();
    float inv = s_inv;

    float4 s0 = sc4[t], s1 = sc4[t + 256];
    orow[2*t]           = __floats2half2_rn(v0.x * inv * s0.x, v0.y * inv * s0.y);
    orow[2*t + 1]       = __floats2half2_rn(v0.z * inv * s0.z, v0.w * inv * s0.w);
    orow[2*(t+256)]     = __floats2half2_rn(v1.x * inv * s1.x, v1.y * inv * s1.y);
    orow[2*(t+256) + 1] = __floats2half2_rn(v1.z * inv * s1.z, v1.w * inv * s1.w);
}

// ---------------- silu(gate) * up -> half ----------------
__global__ void silu_mul_kernel(const float* __restrict__ g, const float* __restrict__ u,
                                __half* __restrict__ out) {
    size_t i = (size_t)blockIdx.x * blockDim.x + threadIdx.x;
    float4 gv = ((const float4*)g)[i];
    float4 uv = ((const float4*)u)[i];
    float r0 = gv.x / (1.f + __expf(-gv.x)) * uv.x;
    float r1 = gv.y / (1.f + __expf(-gv.y)) * uv.y;
    float r2 = gv.z / (1.f + __expf(-gv.z)) * uv.z;
    float r3 = gv.w / (1.f + __expf(-gv.w)) * uv.w;
    ((__half2*)out)[2*i]     = __floats2half2_rn(r0, r1);
    ((__half2*)out)[2*i + 1] = __floats2half2_rn(r2, r3);
}

// ---------------- launch ----------------
extern "C" void kernel_launch(void* const* d_in, const int* in_sizes, int n_in,
                              void* d_out, int out_size) {
    (void)in_sizes; (void)n_in; (void)out_size;
    const float* x      = (const float*)d_in[0];
    const float* w_qkv  = (const float*)d_in[1];
    const float* w_o    = (const float*)d_in[2];
    const float* w_gate = (const float*)d_in[3];
    const float* w_up   = (const float*)d_in[4];
    const float* w_down = (const float*)d_in[5];
    const float* rms1   = (const float*)d_in[6];
    const float* rms2   = (const float*)d_in[7];
    float* out = (float*)d_out;

    __half *h, *qkvh, *vT, *attn, *gateh, *wq, *wo, *wg, *wu, *wd;
    float *x1, *gate, *up;
    cudaGetSymbolAddress((void**)&h,     g_h);
    cudaGetSymbolAddress((void**)&qkvh,  g_qkvh);
    cudaGetSymbolAddress((void**)&vT,    g_vT);
    cudaGetSymbolAddress((void**)&attn,  g_attn);
    cudaGetSymbolAddress((void**)&x1,    g_x1);
    cudaGetSymbolAddress((void**)&gate,  g_gate);
    cudaGetSymbolAddress((void**)&up,    g_up);
    cudaGetSymbolAddress((void**)&gateh, g_gateh);
    cudaGetSymbolAddress((void**)&wq,    g_wqT);
    cudaGetSymbolAddress((void**)&wo,    g_woT);
    cudaGetSymbolAddress((void**)&wg,    g_wgT);
    cudaGetSymbolAddress((void**)&wu,    g_wuT);
    cudaGetSymbolAddress((void**)&wd,    g_wdT);

    cudaFuncSetAttribute(attn_mma_kernel,
                         cudaFuncAttributeMaxDynamicSharedMemorySize, ATTN_SMEM);
    cudaFuncSetAttribute(gemm_mma_kernel<0>,
                         cudaFuncAttributeMaxDynamicSharedMemorySize, GEMM_SMEM);
    cudaFuncSetAttribute(gemm_mma_kernel<1>,
                         cudaFuncAttributeMaxDynamicSharedMemorySize, GEMM_SMEM);
    cudaFuncSetAttribute(gemm_mma_kernel<3>,
                         cudaFuncAttributeMaxDynamicSharedMemorySize, GEMM_SMEM);

    dim3 tb(32, 8);
    convT_kernel<<<dim3((3*H_*HD_)/32, D_/32), tb>>>(w_qkv, wq, D_, 3*H_*HD_);  // 1
    convT_kernel<<<dim3(D_/32, D_/32), tb>>>(w_o, wo, D_, D_);                  // 2
    rmsnorm_kernel<<<NR, 256>>>(x, rms1, h);                                    // 3
    gemm_mma_kernel<3><<<dim3((3*H_*HD_)/256, NR/128), 256, GEMM_SMEM>>>(
        h, wq, nullptr, (float*)qkvh, 3*H_*HD_, D_);                            // 4
    vT_kernel<<<dim3(S_/32, HD_/32, B_*H_), dim3(32, 8)>>>(qkvh, vT);           // 5
    attn_mma_kernel<<<dim3(S_/ABR, H_, B_), 256, ATTN_SMEM>>>(qkvh, vT, attn);  // 6
    gemm_mma_kernel<1><<<dim3(D_/256, NR/128), 256, GEMM_SMEM>>>(
        attn, wo, x, x1, D_, D_);                                               // 7
    rmsnorm_kernel<<<NR, 256>>>(x1, rms2, h);                                   // 8
    convT_kernel<<<dim3(MFF/32, D_/32), tb>>>(w_gate, wg, D_, MFF);             // 9
    convT_kernel<<<dim3(MFF/32, D_/32), tb>>>(w_up,   wu, D_, MFF);             // 10
    convT_kernel<<<dim3(D_/32, MFF/32), tb>>>(w_down, wd, MFF, D_);             // 11
    gemm_mma_kernel<0><<<dim3(MFF/256, NR/128), 256, GEMM_SMEM>>>(
        h, wg, nullptr, gate, MFF, D_);                                         // 12
    gemm_mma_kernel<0><<<dim3(MFF/256, NR/128), 256, GEMM_SMEM>>>(
        h, wu, nullptr, up, MFF, D_);                                           // 13
    silu_mul_kernel<<<(unsigned)((size_t)NR * MFF / 4 / 256), 256>>>(gate, up, gateh); // 14
    gemm_mma_kernel<1><<<dim3(D_/256, NR/128), 256, GEMM_SMEM>>>(
        gateh, wd, x1, out, D_, MFF);                                           // 15
}

// round 16
// speedup vs baseline: 1.0936x; 1.0438x over previous
#include <cuda_runtime.h>
#include <cuda_fp16.h>
#include <math.h>
#include <stdint.h>

#define B_   2
#define S_   2048
#define D_   2048
#define H_   16
#define HD_  128
#define MFF  8192
#define NR   (B_*S_)          // 4096 rows

// ---------------- scratch (static device globals; no allocation) ----------------
__device__ __half g_h    [(size_t)NR * D_];            // rmsnorm out (half)
__device__ __half g_qkvh [(size_t)NR * 3 * H_ * HD_];  // qkv (half)
__device__ __half g_vT   [(size_t)B_ * H_ * HD_ * S_]; // V transposed [b][h][d][s]
__device__ __half g_attn [(size_t)NR * D_];            // attention out (half)
__device__ float  g_x1   [(size_t)NR * D_];
__device__ float  g_gate [(size_t)NR * MFF];
__device__ float  g_up   [(size_t)NR * MFF];
__device__ __half g_gateh[(size_t)NR * MFF];
// half, transposed weights wT[n][k]
__device__ __half g_wqT[(size_t)(3 * H_ * HD_) * D_];
__device__ __half g_woT[(size_t)D_ * D_];
__device__ __half g_wgT[(size_t)MFF * D_];
__device__ __half g_wuT[(size_t)MFF * D_];
__device__ __half g_wdT[(size_t)D_ * MFF];

// ================= helpers =================
__device__ __forceinline__ uint32_t smem_u32(const void* p) {
    uint32_t a;
    asm("{ .reg .u64 t; cvta.to.shared.u64 t, %1; cvt.u32.u64 %0, t; }" : "=r"(a) : "l"(p));
    return a;
}
__device__ __forceinline__ void cp_async16(uint32_t dst, const void* src) {
    asm volatile("cp.async.cg.shared.global [%0], [%1], 16;" :: "r"(dst), "l"(src) : "memory");
}
__device__ __forceinline__ void mma_f16(float* c, const uint32_t* a, const uint32_t* b) {
    asm volatile(
        "mma.sync.aligned.m16n8k16.row.col.f32.f16.f16.f32 "
        "{%0,%1,%2,%3}, {%4,%5,%6,%7}, {%8,%9}, {%0,%1,%2,%3};"
        : "+f"(c[0]), "+f"(c[1]), "+f"(c[2]), "+f"(c[3])
        : "r"(a[0]), "r"(a[1]), "r"(a[2]), "r"(a[3]), "r"(b[0]), "r"(b[1]));
}
__device__ __forceinline__ void ldsm4(uint32_t* r, uint32_t addr) {
    asm volatile("ldmatrix.sync.aligned.m8n8.x4.shared.b16 {%0,%1,%2,%3}, [%4];"
        : "=r"(r[0]), "=r"(r[1]), "=r"(r[2]), "=r"(r[3]) : "r"(addr));
}

// ---------------- weight convert + transpose: fp32 [K][N] -> half [N][K] --------
__global__ void convT_kernel(const float* __restrict__ in, __half* __restrict__ out,
                             int K, int N) {
    __shared__ float tile[32][33];
    int n0 = blockIdx.x * 32, k0 = blockIdx.y * 32;
    int tx = threadIdx.x, ty = threadIdx.y;
    #pragma unroll
    for (int j = 0; j < 32; j += 8)
        tile[ty + j][tx] = in[(size_t)(k0 + ty + j) * N + n0 + tx];
    __syncthreads();
    #pragma unroll
    for (int j = 0; j < 32; j += 8)
        out[(size_t)(n0 + ty + j) * K + k0 + tx] = __float2half_rn(tile[tx][ty + j]);
}

// ---------------- V transpose: qkvh [b][s][3][H][HD] -> vT [b][h][d][s] ----------
__global__ void vT_kernel(const __half* __restrict__ qkvh, __half* __restrict__ out) {
    __shared__ float tile[32][33];
    int bh = blockIdx.z;
    int b = bh >> 4, h = bh & 15;
    int s0 = blockIdx.x * 32, d0 = blockIdx.y * 32;
    int tx = threadIdx.x, ty = threadIdx.y;
    #pragma unroll
    for (int j = 0; j < 32; j += 8)
        tile[ty + j][tx] = __half2float(
            qkvh[(((size_t)b * S_ + s0 + ty + j) * 3 * H_ + 2 * H_ + h) * HD_ + d0 + tx]);
    __syncthreads();
    #pragma unroll
    for (int j = 0; j < 32; j += 8)
        out[(((size_t)bh * HD_) + d0 + ty + j) * S_ + s0 + tx] =
            __float2half_rn(tile[tx][ty + j]);
}

// ================= fp16 mma.sync GEMM: C[M][N] = A[M][K] @ BT[N][K]^T (+epi) =====
// CTA tile 128x256, K-slab 128 (16 barrier pairs at K=2048), double buffered.
// 256 threads = 8 warps 2(M)x4(N); warp tile 64x64; ldmatrix fragment loads.
#define HST 136                        // halfs per row (128 data + 8 pad); 68w == 4 mod 32
#define A_STGH (128 * HST)             // 17408 halfs / stage
#define B_STGH (256 * HST)             // 34816 halfs / stage
#define B_BASEH (2 * A_STGH)
#define GEMM_SMEM ((2 * A_STGH + 2 * B_STGH) * 2)   // 208896 bytes

__device__ __forceinline__ void load_stage(
    uint32_t sb, const __half* Ag, const __half* Bg, int K,
    int t, int stage, int ks)
{
    uint32_t abase = sb + (uint32_t)(stage * A_STGH) * 2;
    uint32_t bbase = sb + (uint32_t)(B_BASEH + stage * B_STGH) * 2;
    #pragma unroll
    for (int i = 0; i < 8; i++) {              // A: 128 rows x 16 granules of 16B
        int idx = i * 256 + t;
        int r = idx >> 4, g = idx & 15;
        cp_async16(abase + (uint32_t)(r * HST + g * 8) * 2,
                   Ag + (size_t)r * K + ks + g * 8);
    }
    #pragma unroll
    for (int i = 0; i < 16; i++) {             // B: 256 rows x 16 granules of 16B
        int idx = i * 256 + t;
        int r = idx >> 4, g = idx & 15;
        cp_async16(bbase + (uint32_t)(r * HST + g * 8) * 2,
                   Bg + (size_t)r * K + ks + g * 8);
    }
    asm volatile("cp.async.commit_group;" ::: "memory");
}

// EPI: 0: fp32 C=A@B   1: fp32 C=A@B+Res   3: half C=A@B
template<int EPI>
__global__ void __launch_bounds__(256, 1)
gemm_mma_kernel(const __half* __restrict__ A, const __half* __restrict__ BT,
                const float* __restrict__ Res, float* __restrict__ C,
                int N, int K)
{
    extern __shared__ __half smh[];
    uint32_t sb = smem_u32(smh);

    int t   = threadIdx.x;
    int w   = t >> 5, lane = t & 31;
    int G   = lane >> 2, T = lane & 3;
    int wm  = w >> 2, wn = w & 3;            // warp grid 2(M) x 4(N)
    int bm  = blockIdx.y, bn = blockIdx.x;

    const __half* Ag = A  + (size_t)bm * 128 * K;
    const __half* Bg = BT + (size_t)bn * 256 * K;
    const int nsteps = K / 128;

    // ldmatrix per-thread address offsets (bytes)
    const uint32_t a_off = (uint32_t)(((wm * 64 + (lane & 15)) * HST
                                       + ((lane >> 4) << 3)) * 2);
    const uint32_t b_off = (uint32_t)(((wn * 64 + ((lane >> 4) << 3) + (lane & 7)) * HST
                                       + (((lane >> 3) & 1) << 3)) * 2);

    float acc[4][8][4];
    #pragma unroll
    for (int i = 0; i < 4; i++)
        #pragma unroll
        for (int j = 0; j < 8; j++)
            #pragma unroll
            for (int r = 0; r < 4; r++) acc[i][j][r] = 0.f;

    load_stage(sb, Ag, Bg, K, t, 0, 0);
    load_stage(sb, Ag, Bg, K, t, 1, 128);

    for (int it = 0; it < nsteps; it++) {
        int cur = it & 1;
        if (it == nsteps - 1) asm volatile("cp.async.wait_group 0;" ::: "memory");
        else                  asm volatile("cp.async.wait_group 1;" ::: "memory");
        __syncthreads();

        uint32_t abase = sb + (uint32_t)(cur * A_STGH) * 2 + a_off;
        uint32_t bbase = sb + (uint32_t)((B_BASEH + cur * B_STGH)) * 2 + b_off;

        #pragma unroll
        for (int kk = 0; kk < 8; kk++) {
            uint32_t kbb = (uint32_t)(kk * 16 * 2);   // byte offset for this K-16 step
            uint32_t af[4][4];
            #pragma unroll
            for (int i = 0; i < 4; i++)
                ldsm4(af[i], abase + (uint32_t)(i * 16 * HST) * 2 + kbb);
            uint32_t bf[8][2];
            #pragma unroll
            for (int jj = 0; jj < 4; jj++) {
                uint32_t r[4];
                ldsm4(r, bbase + (uint32_t)(jj * 16 * HST) * 2 + kbb);
                bf[2 * jj    ][0] = r[0]; bf[2 * jj    ][1] = r[1];
                bf[2 * jj + 1][0] = r[2]; bf[2 * jj + 1][1] = r[3];
            }
            #pragma unroll
            for (int i = 0; i < 4; i++)
                #pragma unroll
                for (int j = 0; j < 8; j++)
                    mma_f16(acc[i][j], af[i], bf[j]);
        }
        __syncthreads();
        if (it + 2 < nsteps)
            load_stage(sb, Ag, Bg, K, t, cur, (it + 2) * 128);
    }

    #pragma unroll
    for (int i = 0; i < 4; i++) {
        int row = bm * 128 + wm * 64 + i * 16 + G;
        #pragma unroll
        for (int j = 0; j < 8; j++) {
            int col = bn * 256 + wn * 64 + j * 8 + 2 * T;
            size_t o0 = (size_t)row * N + col;
            size_t o1 = (size_t)(row + 8) * N + col;
            float2 v0 = make_float2(acc[i][j][0], acc[i][j][1]);
            float2 v1 = make_float2(acc[i][j][2], acc[i][j][3]);
            if (EPI == 1) {
                float2 r0 = *(const float2*)(Res + o0);
                float2 r1 = *(const float2*)(Res + o1);
                v0.x += r0.x; v0.y += r0.y;
                v1.x += r1.x; v1.y += r1.y;
            }
            if (EPI == 3) {
                *(__half2*)((__half*)C + o0) = __floats2half2_rn(v0.x, v0.y);
                *(__half2*)((__half*)C + o1) = __floats2half2_rn(v1.x, v1.y);
            } else {
                *(float2*)(C + o0) = v0;
                *(float2*)(C + o1) = v1;
            }
        }
    }
}

// ================= fp16 tensor-core flash attention (causal) =================
#define ABR 128
#define ABC 64
#define QSTH 136    // Q/K row halfs: 68 words == 4 mod 32 -> banks 4G+T
#define VSTH 72     // V^T/P row halfs: 36 words == 4 mod 32
#define PSTH 72
#define KVH_STG (64 * QSTH + 128 * VSTH)               // 17920 halfs per stage
#define ATTN_SMEM ((2 * KVH_STG + ABR * PSTH) * 2)     // 90112 bytes

__device__ __forceinline__ void attn_load_kv(
    uint32_t sb, const __half* kbase, const __half* vtbase, int t, int stage, int k0)
{
    const size_t rs = (size_t)3 * H_ * HD_;
    uint32_t kdst = sb + (uint32_t)(stage * KVH_STG) * 2;
    uint32_t vdst = kdst + (uint32_t)(64 * QSTH) * 2;
    #pragma unroll
    for (int i = 0; i < 4; i++) {
        int idx = i * 256 + t;
        int r = idx >> 4, g = idx & 15;
        cp_async16(kdst + (uint32_t)(r * QSTH + g * 8) * 2,
                   kbase + (size_t)(k0 + r) * rs + g * 8);
    }
    #pragma unroll
    for (int i = 0; i < 4; i++) {
        int idx = i * 256 + t;
        int r = idx >> 3, g = idx & 7;
        cp_async16(vdst + (uint32_t)(r * VSTH + g * 8) * 2,
                   vtbase + (size_t)r * S_ + k0 + g * 8);
    }
    asm volatile("cp.async.commit_group;" ::: "memory");
}

__global__ void __launch_bounds__(256, 1)
attn_mma_kernel(const __half* __restrict__ qkvh, const __half* __restrict__ vT,
                __half* __restrict__ out) {
    extern __shared__ __half smh[];
    uint32_t sb = smem_u32(smh);
    int t = threadIdx.x, w = t >> 5, lane = t & 31;
    int G = lane >> 2, T = lane & 3;
    int qb = blockIdx.x, h = blockIdx.y, b = blockIdx.z;
    int q0 = qb * ABR;

    const size_t rs = (size_t)3 * H_ * HD_;
    const __half* qbase  = qkvh + (((size_t)b * S_ + q0) * 3 * H_ + h) * HD_;
    const __half* kbase  = qkvh + (((size_t)b * S_) * 3 * H_ + H_ + h) * HD_;
    const __half* vtbase = vT + ((size_t)(b * H_ + h) * HD_) * S_;
    const float scale = 0.08838834764831845f;   // 1/sqrt(128)

    // ---- Q tile (128 rows x 128 d, half) -> smem stage0 region ----
    #pragma unroll
    for (int i = 0; i < 8; i++) {
        int idx = i * 256 + t;
        int r = idx >> 4, g = idx & 15;
        cp_async16(sb + (uint32_t)(r * QSTH + g * 8) * 2,
                   qbase + (size_t)r * rs + g * 8);
    }
    asm volatile("cp.async.commit_group;" ::: "memory");
    asm volatile("cp.async.wait_group 0;" ::: "memory");
    __syncthreads();

    uint32_t qf[8][4];
    {
        int m0 = w * 16 + G;
        #pragma unroll
        for (int kk = 0; kk < 8; kk++) {
            const __half* ar0 = smh + m0 * QSTH + kk * 16 + 2 * T;
            const __half* ar1 = smh + (m0 + 8) * QSTH + kk * 16 + 2 * T;
            qf[kk][0] = *(const uint32_t*)(ar0);
            qf[kk][1] = *(const uint32_t*)(ar1);
            qf[kk][2] = *(const uint32_t*)(ar0 + 8);
            qf[kk][3] = *(const uint32_t*)(ar1 + 8);
        }
    }
    __syncthreads();

    __half* Ps = smh + 2 * KVH_STG;
    const int ntiles = 2 * qb + 2;
    const int qg0 = q0 + w * 16 + G;
    const int qg1 = qg0 + 8;

    float o[16][4];
    #pragma unroll
    for (int j = 0; j < 16; j++)
        #pragma unroll
        for (int r = 0; r < 4; r++) o[j][r] = 0.f;
    float m0r = -INFINITY, m1r = -INFINITY, l0r = 0.f, l1r = 0.f;

    attn_load_kv(sb, kbase, vtbase, t, 0, 0);
    attn_load_kv(sb, kbase, vtbase, t, 1, ABC);

    for (int kt = 0; kt < ntiles; kt++) {
        int cur = kt & 1;
        if (kt == ntiles - 1) asm volatile("cp.async.wait_group 0;" ::: "memory");
        else                  asm volatile("cp.async.wait_group 1;" ::: "memory");
        __syncthreads();

        const __half* Ks = smh + cur * KVH_STG;
        const __half* Vs = Ks + 64 * QSTH;
        int k0 = kt * ABC;

        // ---- S = Q K^T ----
        float s[8][4];
        #pragma unroll
        for (int j = 0; j < 8; j++)
            #pragma unroll
            for (int r = 0; r < 4; r++) s[j][r] = 0.f;

        #pragma unroll
        for (int kk = 0; kk < 8; kk++) {
            int kb = kk * 16;
            #pragma unroll
            for (int j = 0; j < 8; j++) {
                const __half* br = Ks + (j * 8 + G) * QSTH + kb + 2 * T;
                uint32_t bf[2];
                bf[0] = *(const uint32_t*)(br);
                bf[1] = *(const uint32_t*)(br + 8);
                mma_f16(s[j], qf[kk], bf);
            }
        }

        // ---- online softmax ----
        bool domask = (kt >= 2 * qb);
        float mx0 = -INFINITY, mx1 = -INFINITY;
        #pragma unroll
        for (int j = 0; j < 8; j++) {
            s[j][0] *= scale; s[j][1] *= scale; s[j][2] *= scale; s[j][3] *= scale;
            if (domask) {
                int kv = k0 + j * 8 + 2 * T;
                if (kv     > qg0) s[j][0] = -INFINITY;
                if (kv + 1 > qg0) s[j][1] = -INFINITY;
                if (kv     > qg1) s[j][2] = -INFINITY;
                if (kv + 1 > qg1) s[j][3] = -INFINITY;
            }
            mx0 = fmaxf(mx0, fmaxf(s[j][0], s[j][1]));
            mx1 = fmaxf(mx1, fmaxf(s[j][2], s[j][3]));
        }
        mx0 = fmaxf(mx0, __shfl_xor_sync(0xffffffffu, mx0, 1));
        mx0 = fmaxf(mx0, __shfl_xor_sync(0xffffffffu, mx0, 2));
        mx1 = fmaxf(mx1, __shfl_xor_sync(0xffffffffu, mx1, 1));
        mx1 = fmaxf(mx1, __shfl_xor_sync(0xffffffffu, mx1, 2));

        float mn0 = fmaxf(m0r, mx0), mn1 = fmaxf(m1r, mx1);
        float a0 = __expf(m0r - mn0), a1 = __expf(m1r - mn1);
        m0r = mn0; m1r = mn1;

        __syncwarp();
        float rs0 = 0.f, rs1 = 0.f;
        #pragma unroll
        for (int j = 0; j < 8; j++) {
            float p0 = __expf(s[j][0] - mn0);
            float p1 = __expf(s[j][1] - mn0);
            float p2 = __expf(s[j][2] - mn1);
            float p3 = __expf(s[j][3] - mn1);
            rs0 += p0 + p1; rs1 += p2 + p3;
            int c = j * 8 + 2 * T;
            *(__half2*)(&Ps[(w * 16 + G    ) * PSTH + c]) = __floats2half2_rn(p0, p1);
            *(__half2*)(&Ps[(w * 16 + G + 8) * PSTH + c]) = __floats2half2_rn(p2, p3);
        }
        rs0 += __shfl_xor_sync(0xffffffffu, rs0, 1);
        rs0 += __shfl_xor_sync(0xffffffffu, rs0, 2);
        rs1 += __shfl_xor_sync(0xffffffffu, rs1, 1);
        rs1 += __shfl_xor_sync(0xffffffffu, rs1, 2);
        l0r = l0r * a0 + rs0;
        l1r = l1r * a1 + rs1;

        #pragma unroll
        for (int j = 0; j < 16; j++) {
            o[j][0] *= a0; o[j][1] *= a0;
            o[j][2] *= a1; o[j][3] *= a1;
        }
        __syncwarp();

        // ---- O += P @ V ----
        #pragma unroll
        for (int kc = 0; kc < 4; kc++) {
            int kb = kc * 16;
            const __half* pr0 = Ps + (w * 16 + G) * PSTH + kb + 2 * T;
            const __half* pr1 = Ps + (w * 16 + G + 8) * PSTH + kb + 2 * T;
            uint32_t af[4];
            af[0] = *(const uint32_t*)(pr0);
            af[1] = *(const uint32_t*)(pr1);
            af[2] = *(const uint32_t*)(pr0 + 8);
            af[3] = *(const uint32_t*)(pr1 + 8);
            #pragma unroll
            for (int j = 0; j < 16; j++) {
                const __half* br = Vs + (j * 8 + G) * VSTH + kb + 2 * T;
                uint32_t bf[2];
                bf[0] = *(const uint32_t*)(br);
                bf[1] = *(const uint32_t*)(br + 8);
                mma_f16(o[j], af, bf);
            }
        }
        __syncthreads();
        if (kt + 2 < ntiles)
            attn_load_kv(sb, kbase, vtbase, t, cur, (kt + 2) * ABC);
    }

    // ---- write O / l as half ----
    float i0 = 1.0f / l0r, i1 = 1.0f / l1r;
    #pragma unroll
    for (int j = 0; j < 16; j++) {
        int col = h * HD_ + j * 8 + 2 * T;
        size_t o0 = ((size_t)b * S_ + qg0) * D_ + col;
        size_t o1 = ((size_t)b * S_ + qg1) * D_ + col;
        *(__half2*)(out + o0) = __floats2half2_rn(o[j][0] * i0, o[j][1] * i0);
        *(__half2*)(out + o1) = __floats2half2_rn(o[j][2] * i1, o[j][3] * i1);
    }
}

// ---------------- RMSNorm (writes half) ----------------
__global__ void rmsnorm_kernel(const float* __restrict__ x,
                               const float* __restrict__ sc,
                               __half* __restrict__ o) {
    int row = blockIdx.x;
    const float4* xr  = (const float4*)(x + (size_t)row * D_);
    __half2* orow     = (__half2*)(o + (size_t)row * D_);
    const float4* sc4 = (const float4*)sc;
    int t = threadIdx.x;

    float4 v0 = xr[t];
    float4 v1 = xr[t + 256];
    float ss = v0.x*v0.x + v0.y*v0.y + v0.z*v0.z + v0.w*v0.w
             + v1.x*v1.x + v1.y*v1.y + v1.z*v1.z + v1.w*v1.w;
    #pragma unroll
    for (int off = 16; off > 0; off >>= 1)
        ss += __shfl_xor_sync(0xffffffffu, ss, off);

    __shared__ float red[8];
    __shared__ float s_inv;
    if ((t & 31) == 0) red[t >> 5] = ss;
    __syncthreads();
    if (t == 0) {
        float tot = 0.f;
        #pragma unroll
        for (int i = 0; i < 8; i++) tot += red[i];
        s_inv = rsqrtf(tot * (1.0f / (float)D_) + 1e-6f);
    }
    __syncthreads();
    float inv = s_inv;

    float4 s0 = sc4[t], s1 = sc4[t + 256];
    orow[2*t]           = __floats2half2_rn(v0.x * inv * s0.x, v0.y * inv * s0.y);
    orow[2*t + 1]       = __floats2half2_rn(v0.z * inv * s0.z, v0.w * inv * s0.w);
    orow[2*(t+256)]     = __floats2half2_rn(v1.x * inv * s1.x, v1.y * inv * s1.y);
    orow[2*(t+256) + 1] = __floats2half2_rn(v1.z * inv * s1.z, v1.w * inv * s1.w);
}

// ---------------- silu(gate) * up -> half ----------------
__global__ void silu_mul_kernel(const float* __restrict__ g, const float* __restrict__ u,
                                __half* __restrict__ out) {
    size_t i = (size_t)blockIdx.x * blockDim.x + threadIdx.x;
    float4 gv = ((const float4*)g)[i];
    float4 uv = ((const float4*)u)[i];
    float r0 = gv.x / (1.f + __expf(-gv.x)) * uv.x;
    float r1 = gv.y / (1.f + __expf(-gv.y)) * uv.y;
    float r2 = gv.z / (1.f + __expf(-gv.z)) * uv.z;
    float r3 = gv.w / (1.f + __expf(-gv.w)) * uv.w;
    ((__half2*)out)[2*i]     = __floats2half2_rn(r0, r1);
    ((__half2*)out)[2*i + 1] = __floats2half2_rn(r2, r3);
}

// ---------------- launch ----------------
extern "C" void kernel_launch(void* const* d_in, const int* in_sizes, int n_in,
                              void* d_out, int out_size) {
    (void)in_sizes; (void)n_in; (void)out_size;
    const float* x      = (const float*)d_in[0];
    const float* w_qkv  = (const float*)d_in[1];
    const float* w_o    = (const float*)d_in[2];
    const float* w_gate = (const float*)d_in[3];
    const float* w_up   = (const float*)d_in[4];
    const float* w_down = (const float*)d_in[5];
    const float* rms1   = (const float*)d_in[6];
    const float* rms2   = (const float*)d_in[7];
    float* out = (float*)d_out;

    __half *h, *qkvh, *vT, *attn, *gateh, *wq, *wo, *wg, *wu, *wd;
    float *x1, *gate, *up;
    cudaGetSymbolAddress((void**)&h,     g_h);
    cudaGetSymbolAddress((void**)&qkvh,  g_qkvh);
    cudaGetSymbolAddress((void**)&vT,    g_vT);
    cudaGetSymbolAddress((void**)&attn,  g_attn);
    cudaGetSymbolAddress((void**)&x1,    g_x1);
    cudaGetSymbolAddress((void**)&gate,  g_gate);
    cudaGetSymbolAddress((void**)&up,    g_up);
    cudaGetSymbolAddress((void**)&gateh, g_gateh);
    cudaGetSymbolAddress((void**)&wq,    g_wqT);
    cudaGetSymbolAddress((void**)&wo,    g_woT);
    cudaGetSymbolAddress((void**)&wg,    g_wgT);
    cudaGetSymbolAddress((void**)&wu,    g_wuT);
    cudaGetSymbolAddress((void**)&wd,    g_wdT);

    cudaFuncSetAttribute(attn_mma_kernel,
                         cudaFuncAttributeMaxDynamicSharedMemorySize, ATTN_SMEM);
    cudaFuncSetAttribute(gemm_mma_kernel<0>,
                         cudaFuncAttributeMaxDynamicSharedMemorySize, GEMM_SMEM);
    cudaFuncSetAttribute(gemm_mma_kernel<1>,
                         cudaFuncAttributeMaxDynamicSharedMemorySize, GEMM_SMEM);
    cudaFuncSetAttribute(gemm_mma_kernel<3>,
                         cudaFuncAttributeMaxDynamicSharedMemorySize, GEMM_SMEM);

    dim3 tb(32, 8);
    convT_kernel<<<dim3((3*H_*HD_)/32, D_/32), tb>>>(w_qkv, wq, D_, 3*H_*HD_);  // 1
    convT_kernel<<<dim3(D_/32, D_/32), tb>>>(w_o, wo, D_, D_);                  // 2
    rmsnorm_kernel<<<NR, 256>>>(x, rms1, h);                                    // 3
    gemm_mma_kernel<3><<<dim3((3*H_*HD_)/256, NR/128), 256, GEMM_SMEM>>>(
        h, wq, nullptr, (float*)qkvh, 3*H_*HD_, D_);                            // 4
    vT_kernel<<<dim3(S_/32, HD_/32, B_*H_), dim3(32, 8)>>>(qkvh, vT);           // 5
    attn_mma_kernel<<<dim3(S_/ABR, H_, B_), 256, ATTN_SMEM>>>(qkvh, vT, attn);  // 6
    gemm_mma_kernel<1><<<dim3(D_/256, NR/128), 256, GEMM_SMEM>>>(
        attn, wo, x, x1, D_, D_);                                               // 7
    rmsnorm_kernel<<<NR, 256>>>(x1, rms2, h);                                   // 8
    convT_kernel<<<dim3(MFF/32, D_/32), tb>>>(w_gate, wg, D_, MFF);             // 9
    convT_kernel<<<dim3(MFF/32, D_/32), tb>>>(w_up,   wu, D_, MFF);             // 10
    convT_kernel<<<dim3(D_/32, MFF/32), tb>>>(w_down, wd, MFF, D_);             // 11
    gemm_mma_kernel<0><<<dim3(MFF/256, NR/128), 256, GEMM_SMEM>>>(
        h, wg, nullptr, gate, MFF, D_);                                         // 12
    gemm_mma_kernel<0><<<dim3(MFF/256, NR/128), 256, GEMM_SMEM>>>(
        h, wu, nullptr, up, MFF, D_);                                           // 13
    silu_mul_kernel<<<(unsigned)((size_t)NR * MFF / 4 / 256), 256>>>(gate, up, gateh); // 14
    gemm_mma_kernel<1><<<dim3(D_/256, NR/128), 256, GEMM_SMEM>>>(
        gateh, wd, x1, out, D_, MFF);                                           // 15
}

// round 17
// speedup vs baseline: 1.1079x; 1.0131x over previous
#include <cuda_runtime.h>
#include <cuda_fp16.h>
#include <math.h>
#include <stdint.h>

#define B_   2
#define S_   2048
#define D_   2048
#define H_   16
#define HD_  128
#define MFF  8192
#define NR   (B_*S_)          // 4096 rows

// ---------------- scratch (static device globals; no allocation) ----------------
__device__ __half g_h    [(size_t)NR * D_];            // rmsnorm out (half)
__device__ __half g_qkvh [(size_t)NR * 3 * H_ * HD_];  // qkv (half)
__device__ __half g_vT   [(size_t)B_ * H_ * HD_ * S_]; // V transposed [b][h][d][s]
__device__ __half g_attn [(size_t)NR * D_];            // attention out (half)
__device__ float  g_x1   [(size_t)NR * D_];
__device__ float  g_gate [(size_t)NR * MFF];
__device__ float  g_up   [(size_t)NR * MFF];
__device__ __half g_gateh[(size_t)NR * MFF];
// half, transposed weights wT[n][k]
__device__ __half g_wqT[(size_t)(3 * H_ * HD_) * D_];
__device__ __half g_woT[(size_t)D_ * D_];
__device__ __half g_wgT[(size_t)MFF * D_];
__device__ __half g_wuT[(size_t)MFF * D_];
__device__ __half g_wdT[(size_t)D_ * MFF];

// ================= helpers =================
__device__ __forceinline__ uint32_t smem_u32(const void* p) {
    uint32_t a;
    asm("{ .reg .u64 t; cvta.to.shared.u64 t, %1; cvt.u32.u64 %0, t; }" : "=r"(a) : "l"(p));
    return a;
}
__device__ __forceinline__ void cp_async16(uint32_t dst, const void* src) {
    asm volatile("cp.async.cg.shared.global [%0], [%1], 16;" :: "r"(dst), "l"(src) : "memory");
}
__device__ __forceinline__ void mma_f16(float* c, const uint32_t* a, const uint32_t* b) {
    asm volatile(
        "mma.sync.aligned.m16n8k16.row.col.f32.f16.f16.f32 "
        "{%0,%1,%2,%3}, {%4,%5,%6,%7}, {%8,%9}, {%0,%1,%2,%3};"
        : "+f"(c[0]), "+f"(c[1]), "+f"(c[2]), "+f"(c[3])
        : "r"(a[0]), "r"(a[1]), "r"(a[2]), "r"(a[3]), "r"(b[0]), "r"(b[1]));
}
__device__ __forceinline__ void ldsm4(uint32_t* r, uint32_t addr) {
    asm volatile("ldmatrix.sync.aligned.m8n8.x4.shared.b16 {%0,%1,%2,%3}, [%4];"
        : "=r"(r[0]), "=r"(r[1]), "=r"(r[2]), "=r"(r[3]) : "r"(addr));
}

// ---------------- weight convert + transpose: fp32 [K][N] -> half [N][K] --------
__global__ void convT_kernel(const float* __restrict__ in, __half* __restrict__ out,
                             int K, int N) {
    __shared__ float tile[32][33];
    int n0 = blockIdx.x * 32, k0 = blockIdx.y * 32;
    int tx = threadIdx.x, ty = threadIdx.y;
    #pragma unroll
    for (int j = 0; j < 32; j += 8)
        tile[ty + j][tx] = in[(size_t)(k0 + ty + j) * N + n0 + tx];
    __syncthreads();
    #pragma unroll
    for (int j = 0; j < 32; j += 8)
        out[(size_t)(n0 + ty + j) * K + k0 + tx] = __float2half_rn(tile[tx][ty + j]);
}

// ---------------- V transpose: qkvh [b][s][3][H][HD] -> vT [b][h][d][s] ----------
__global__ void vT_kernel(const __half* __restrict__ qkvh, __half* __restrict__ out) {
    __shared__ float tile[32][33];
    int bh = blockIdx.z;
    int b = bh >> 4, h = bh & 15;
    int s0 = blockIdx.x * 32, d0 = blockIdx.y * 32;
    int tx = threadIdx.x, ty = threadIdx.y;
    #pragma unroll
    for (int j = 0; j < 32; j += 8)
        tile[ty + j][tx] = __half2float(
            qkvh[(((size_t)b * S_ + s0 + ty + j) * 3 * H_ + 2 * H_ + h) * HD_ + d0 + tx]);
    __syncthreads();
    #pragma unroll
    for (int j = 0; j < 32; j += 8)
        out[(((size_t)bh * HD_) + d0 + ty + j) * S_ + s0 + tx] =
            __float2half_rn(tile[tx][ty + j]);
}

// ================= fp16 mma.sync GEMM: C[M][N] = A[M][K] @ BT[N][K]^T (+epi) =====
// CTA tile 128x128, K-slab 64, double buffered, 2 CTAs/SM (decorrelated barriers).
// 256 threads = 8 warps 2(M)x4(N); warp tile 64x32; ldmatrix fragment loads.
#define HST 72                         // halfs per row (64 data + 8 pad); 36w == 4 mod 32
#define A_STGH (128 * HST)             // 9216 halfs / stage
#define B_STGH (128 * HST)             // 9216 halfs / stage
#define B_BASEH (2 * A_STGH)
#define GEMM_SMEM ((2 * A_STGH + 2 * B_STGH) * 2)   // 73728 bytes -> 2 CTAs/SM

__device__ __forceinline__ void load_stage(
    uint32_t sb, const __half* Ag, const __half* Bg, int K,
    int t, int stage, int ks)
{
    uint32_t abase = sb + (uint32_t)(stage * A_STGH) * 2;
    uint32_t bbase = sb + (uint32_t)(B_BASEH + stage * B_STGH) * 2;
    #pragma unroll
    for (int i = 0; i < 4; i++) {              // A: 128 rows x 8 granules of 16B
        int idx = i * 256 + t;
        int r = idx >> 3, g = idx & 7;
        cp_async16(abase + (uint32_t)(r * HST + g * 8) * 2,
                   Ag + (size_t)r * K + ks + g * 8);
    }
    #pragma unroll
    for (int i = 0; i < 4; i++) {              // B: 128 rows x 8 granules of 16B
        int idx = i * 256 + t;
        int r = idx >> 3, g = idx & 7;
        cp_async16(bbase + (uint32_t)(r * HST + g * 8) * 2,
                   Bg + (size_t)r * K + ks + g * 8);
    }
    asm volatile("cp.async.commit_group;" ::: "memory");
}

// EPI: 0: fp32 C=A@B   1: fp32 C=A@B+Res   3: half C=A@B
template<int EPI>
__global__ void __launch_bounds__(256, 2)
gemm_mma_kernel(const __half* __restrict__ A, const __half* __restrict__ BT,
                const float* __restrict__ Res, float* __restrict__ C,
                int N, int K)
{
    extern __shared__ __half smh[];
    uint32_t sb = smem_u32(smh);

    int t   = threadIdx.x;
    int w   = t >> 5, lane = t & 31;
    int G   = lane >> 2, T = lane & 3;
    int wm  = w >> 2, wn = w & 3;            // warp grid 2(M) x 4(N)
    int bm  = blockIdx.y, bn = blockIdx.x;

    const __half* Ag = A  + (size_t)bm * 128 * K;
    const __half* Bg = BT + (size_t)bn * 128 * K;
    const int nsteps = K / 64;

    // ldmatrix per-thread address offsets (bytes)
    const uint32_t a_off = (uint32_t)(((wm * 64 + (lane & 15)) * HST
                                       + ((lane >> 4) << 3)) * 2);
    const uint32_t b_off = (uint32_t)(((wn * 32 + ((lane >> 4) << 3) + (lane & 7)) * HST
                                       + (((lane >> 3) & 1) << 3)) * 2);

    float acc[4][4][4];
    #pragma unroll
    for (int i = 0; i < 4; i++)
        #pragma unroll
        for (int j = 0; j < 4; j++)
            #pragma unroll
            for (int r = 0; r < 4; r++) acc[i][j][r] = 0.f;

    load_stage(sb, Ag, Bg, K, t, 0, 0);
    load_stage(sb, Ag, Bg, K, t, 1, 64);

    for (int it = 0; it < nsteps; it++) {
        int cur = it & 1;
        if (it == nsteps - 1) asm volatile("cp.async.wait_group 0;" ::: "memory");
        else                  asm volatile("cp.async.wait_group 1;" ::: "memory");
        __syncthreads();

        uint32_t abase = sb + (uint32_t)(cur * A_STGH) * 2 + a_off;
        uint32_t bbase = sb + (uint32_t)((B_BASEH + cur * B_STGH)) * 2 + b_off;

        #pragma unroll
        for (int kk = 0; kk < 4; kk++) {
            uint32_t kbb = (uint32_t)(kk * 16 * 2);
            uint32_t af[4][4];
            #pragma unroll
            for (int i = 0; i < 4; i++)
                ldsm4(af[i], abase + (uint32_t)(i * 16 * HST) * 2 + kbb);
            uint32_t bf[4][2];
            #pragma unroll
            for (int jj = 0; jj < 2; jj++) {
                uint32_t r[4];
                ldsm4(r, bbase + (uint32_t)(jj * 16 * HST) * 2 + kbb);
                bf[2 * jj    ][0] = r[0]; bf[2 * jj    ][1] = r[1];
                bf[2 * jj + 1][0] = r[2]; bf[2 * jj + 1][1] = r[3];
            }
            #pragma unroll
            for (int i = 0; i < 4; i++)
                #pragma unroll
                for (int j = 0; j < 4; j++)
                    mma_f16(acc[i][j], af[i], bf[j]);
        }
        __syncthreads();
        if (it + 2 < nsteps)
            load_stage(sb, Ag, Bg, K, t, cur, (it + 2) * 64);
    }

    #pragma unroll
    for (int i = 0; i < 4; i++) {
        int row = bm * 128 + wm * 64 + i * 16 + G;
        #pragma unroll
        for (int j = 0; j < 4; j++) {
            int col = bn * 128 + wn * 32 + j * 8 + 2 * T;
            size_t o0 = (size_t)row * N + col;
            size_t o1 = (size_t)(row + 8) * N + col;
            float2 v0 = make_float2(acc[i][j][0], acc[i][j][1]);
            float2 v1 = make_float2(acc[i][j][2], acc[i][j][3]);
            if (EPI == 1) {
                float2 r0 = *(const float2*)(Res + o0);
                float2 r1 = *(const float2*)(Res + o1);
                v0.x += r0.x; v0.y += r0.y;
                v1.x += r1.x; v1.y += r1.y;
            }
            if (EPI == 3) {
                *(__half2*)((__half*)C + o0) = __floats2half2_rn(v0.x, v0.y);
                *(__half2*)((__half*)C + o1) = __floats2half2_rn(v1.x, v1.y);
            } else {
                *(float2*)(C + o0) = v0;
                *(float2*)(C + o1) = v1;
            }
        }
    }
}

// ================= fp16 tensor-core flash attention (causal) =================
#define ABR 128
#define ABC 64
#define QSTH 136    // Q/K row halfs: 68 words == 4 mod 32 -> banks 4G+T
#define VSTH 72     // V^T/P row halfs: 36 words == 4 mod 32
#define PSTH 72
#define KVH_STG (64 * QSTH + 128 * VSTH)               // 17920 halfs per stage
#define ATTN_SMEM ((2 * KVH_STG + ABR * PSTH) * 2)     // 90112 bytes

__device__ __forceinline__ void attn_load_kv(
    uint32_t sb, const __half* kbase, const __half* vtbase, int t, int stage, int k0)
{
    const size_t rs = (size_t)3 * H_ * HD_;
    uint32_t kdst = sb + (uint32_t)(stage * KVH_STG) * 2;
    uint32_t vdst = kdst + (uint32_t)(64 * QSTH) * 2;
    #pragma unroll
    for (int i = 0; i < 4; i++) {
        int idx = i * 256 + t;
        int r = idx >> 4, g = idx & 15;
        cp_async16(kdst + (uint32_t)(r * QSTH + g * 8) * 2,
                   kbase + (size_t)(k0 + r) * rs + g * 8);
    }
    #pragma unroll
    for (int i = 0; i < 4; i++) {
        int idx = i * 256 + t;
        int r = idx >> 3, g = idx & 7;
        cp_async16(vdst + (uint32_t)(r * VSTH + g * 8) * 2,
                   vtbase + (size_t)r * S_ + k0 + g * 8);
    }
    asm volatile("cp.async.commit_group;" ::: "memory");
}

__global__ void __launch_bounds__(256, 1)
attn_mma_kernel(const __half* __restrict__ qkvh, const __half* __restrict__ vT,
                __half* __restrict__ out) {
    extern __shared__ __half smh[];
    uint32_t sb = smem_u32(smh);
    int t = threadIdx.x, w = t >> 5, lane = t & 31;
    int G = lane >> 2, T = lane & 3;
    int qb = blockIdx.x, h = blockIdx.y, b = blockIdx.z;
    int q0 = qb * ABR;

    const size_t rs = (size_t)3 * H_ * HD_;
    const __half* qbase  = qkvh + (((size_t)b * S_ + q0) * 3 * H_ + h) * HD_;
    const __half* kbase  = qkvh + (((size_t)b * S_) * 3 * H_ + H_ + h) * HD_;
    const __half* vtbase = vT + ((size_t)(b * H_ + h) * HD_) * S_;
    const float scale = 0.08838834764831845f;   // 1/sqrt(128)

    // ---- Q tile (128 rows x 128 d, half) -> smem stage0 region ----
    #pragma unroll
    for (int i = 0; i < 8; i++) {
        int idx = i * 256 + t;
        int r = idx >> 4, g = idx & 15;
        cp_async16(sb + (uint32_t)(r * QSTH + g * 8) * 2,
                   qbase + (size_t)r * rs + g * 8);
    }
    asm volatile("cp.async.commit_group;" ::: "memory");
    asm volatile("cp.async.wait_group 0;" ::: "memory");
    __syncthreads();

    uint32_t qf[8][4];
    {
        int m0 = w * 16 + G;
        #pragma unroll
        for (int kk = 0; kk < 8; kk++) {
            const __half* ar0 = smh + m0 * QSTH + kk * 16 + 2 * T;
            const __half* ar1 = smh + (m0 + 8) * QSTH + kk * 16 + 2 * T;
            qf[kk][0] = *(const uint32_t*)(ar0);
            qf[kk][1] = *(const uint32_t*)(ar1);
            qf[kk][2] = *(const uint32_t*)(ar0 + 8);
            qf[kk][3] = *(const uint32_t*)(ar1 + 8);
        }
    }
    __syncthreads();

    __half* Ps = smh + 2 * KVH_STG;
    const int ntiles = 2 * qb + 2;
    const int qg0 = q0 + w * 16 + G;
    const int qg1 = qg0 + 8;

    float o[16][4];
    #pragma unroll
    for (int j = 0; j < 16; j++)
        #pragma unroll
        for (int r = 0; r < 4; r++) o[j][r] = 0.f;
    float m0r = -INFINITY, m1r = -INFINITY, l0r = 0.f, l1r = 0.f;

    attn_load_kv(sb, kbase, vtbase, t, 0, 0);
    attn_load_kv(sb, kbase, vtbase, t, 1, ABC);

    for (int kt = 0; kt < ntiles; kt++) {
        int cur = kt & 1;
        if (kt == ntiles - 1) asm volatile("cp.async.wait_group 0;" ::: "memory");
        else                  asm volatile("cp.async.wait_group 1;" ::: "memory");
        __syncthreads();

        const __half* Ks = smh + cur * KVH_STG;
        const __half* Vs = Ks + 64 * QSTH;
        int k0 = kt * ABC;

        // ---- S = Q K^T ----
        float s[8][4];
        #pragma unroll
        for (int j = 0; j < 8; j++)
            #pragma unroll
            for (int r = 0; r < 4; r++) s[j][r] = 0.f;

        #pragma unroll
        for (int kk = 0; kk < 8; kk++) {
            int kb = kk * 16;
            #pragma unroll
            for (int j = 0; j < 8; j++) {
                const __half* br = Ks + (j * 8 + G) * QSTH + kb + 2 * T;
                uint32_t bf[2];
                bf[0] = *(const uint32_t*)(br);
                bf[1] = *(const uint32_t*)(br + 8);
                mma_f16(s[j], qf[kk], bf);
            }
        }

        // ---- online softmax ----
        bool domask = (kt >= 2 * qb);
        float mx0 = -INFINITY, mx1 = -INFINITY;
        #pragma unroll
        for (int j = 0; j < 8; j++) {
            s[j][0] *= scale; s[j][1] *= scale; s[j][2] *= scale; s[j][3] *= scale;
            if (domask) {
                int kv = k0 + j * 8 + 2 * T;
                if (kv     > qg0) s[j][0] = -INFINITY;
                if (kv + 1 > qg0) s[j][1] = -INFINITY;
                if (kv     > qg1) s[j][2] = -INFINITY;
                if (kv + 1 > qg1) s[j][3] = -INFINITY;
            }
            mx0 = fmaxf(mx0, fmaxf(s[j][0], s[j][1]));
            mx1 = fmaxf(mx1, fmaxf(s[j][2], s[j][3]));
        }
        mx0 = fmaxf(mx0, __shfl_xor_sync(0xffffffffu, mx0, 1));
        mx0 = fmaxf(mx0, __shfl_xor_sync(0xffffffffu, mx0, 2));
        mx1 = fmaxf(mx1, __shfl_xor_sync(0xffffffffu, mx1, 1));
        mx1 = fmaxf(mx1, __shfl_xor_sync(0xffffffffu, mx1, 2));

        float mn0 = fmaxf(m0r, mx0), mn1 = fmaxf(m1r, mx1);
        float a0 = __expf(m0r - mn0), a1 = __expf(m1r - mn1);
        m0r = mn0; m1r = mn1;

        __syncwarp();
        float rs0 = 0.f, rs1 = 0.f;
        #pragma unroll
        for (int j = 0; j < 8; j++) {
            float p0 = __expf(s[j][0] - mn0);
            float p1 = __expf(s[j][1] - mn0);
            float p2 = __expf(s[j][2] - mn1);
            float p3 = __expf(s[j][3] - mn1);
            rs0 += p0 + p1; rs1 += p2 + p3;
            int c = j * 8 + 2 * T;
            *(__half2*)(&Ps[(w * 16 + G    ) * PSTH + c]) = __floats2half2_rn(p0, p1);
            *(__half2*)(&Ps[(w * 16 + G + 8) * PSTH + c]) = __floats2half2_rn(p2, p3);
        }
        rs0 += __shfl_xor_sync(0xffffffffu, rs0, 1);
        rs0 += __shfl_xor_sync(0xffffffffu, rs0, 2);
        rs1 += __shfl_xor_sync(0xffffffffu, rs1, 1);
        rs1 += __shfl_xor_sync(0xffffffffu, rs1, 2);
        l0r = l0r * a0 + rs0;
        l1r = l1r * a1 + rs1;

        #pragma unroll
        for (int j = 0; j < 16; j++) {
            o[j][0] *= a0; o[j][1] *= a0;
            o[j][2] *= a1; o[j][3] *= a1;
        }
        __syncwarp();

        // ---- O += P @ V ----
        #pragma unroll
        for (int kc = 0; kc < 4; kc++) {
            int kb = kc * 16;
            const __half* pr0 = Ps + (w * 16 + G) * PSTH + kb + 2 * T;
            const __half* pr1 = Ps + (w * 16 + G + 8) * PSTH + kb + 2 * T;
            uint32_t af[4];
            af[0] = *(const uint32_t*)(pr0);
            af[1] = *(const uint32_t*)(pr1);
            af[2] = *(const uint32_t*)(pr0 + 8);
            af[3] = *(const uint32_t*)(pr1 + 8);
            #pragma unroll
            for (int j = 0; j < 16; j++) {
                const __half* br = Vs + (j * 8 + G) * VSTH + kb + 2 * T;
                uint32_t bf[2];
                bf[0] = *(const uint32_t*)(br);
                bf[1] = *(const uint32_t*)(br + 8);
                mma_f16(o[j], af, bf);
            }
        }
        __syncthreads();
        if (kt + 2 < ntiles)
            attn_load_kv(sb, kbase, vtbase, t, cur, (kt + 2) * ABC);
    }

    // ---- write O / l as half ----
    float i0 = 1.0f / l0r, i1 = 1.0f / l1r;
    #pragma unroll
    for (int j = 0; j < 16; j++) {
        int col = h * HD_ + j * 8 + 2 * T;
        size_t o0 = ((size_t)b * S_ + qg0) * D_ + col;
        size_t o1 = ((size_t)b * S_ + qg1) * D_ + col;
        *(__half2*)(out + o0) = __floats2half2_rn(o[j][0] * i0, o[j][1] * i0);
        *(__half2*)(out + o1) = __floats2half2_rn(o[j][2] * i1, o[j][3] * i1);
    }
}

// ---------------- RMSNorm (writes half) ----------------
__global__ void rmsnorm_kernel(const float* __restrict__ x,
                               const float* __restrict__ sc,
                               __half* __restrict__ o) {
    int row = blockIdx.x;
    const float4* xr  = (const float4*)(x + (size_t)row * D_);
    __half2* orow     = (__half2*)(o + (size_t)row * D_);
    const float4* sc4 = (const float4*)sc;
    int t = threadIdx.x;

    float4 v0 = xr[t];
    float4 v1 = xr[t + 256];
    float ss = v0.x*v0.x + v0.y*v0.y + v0.z*v0.z + v0.w*v0.w
             + v1.x*v1.x + v1.y*v1.y + v1.z*v1.z + v1.w*v1.w;
    #pragma unroll
    for (int off = 16; off > 0; off >>= 1)
        ss += __shfl_xor_sync(0xffffffffu, ss, off);

    __shared__ float red[8];
    __shared__ float s_inv;
    if ((t & 31) == 0) red[t >> 5] = ss;
    __syncthreads();
    if (t == 0) {
        float tot = 0.f;
        #pragma unroll
        for (int i = 0; i < 8; i++) tot += red[i];
        s_inv = rsqrtf(tot * (1.0f / (float)D_) + 1e-6f);
    }
    __syncthreads();
    float inv = s_inv;

    float4 s0 = sc4[t], s1 = sc4[t + 256];
    orow[2*t]           = __floats2half2_rn(v0.x * inv * s0.x, v0.y * inv * s0.y);
    orow[2*t + 1]       = __floats2half2_rn(v0.z * inv * s0.z, v0.w * inv * s0.w);
    orow[2*(t+256)]     = __floats2half2_rn(v1.x * inv * s1.x, v1.y * inv * s1.y);
    orow[2*(t+256) + 1] = __floats2half2_rn(v1.z * inv * s1.z, v1.w * inv * s1.w);
}

// ---------------- silu(gate) * up -> half ----------------
__global__ void silu_mul_kernel(const float* __restrict__ g, const float* __restrict__ u,
                                __half* __restrict__ out) {
    size_t i = (size_t)blockIdx.x * blockDim.x + threadIdx.x;
    float4 gv = ((const float4*)g)[i];
    float4 uv = ((const float4*)u)[i];
    float r0 = gv.x / (1.f + __expf(-gv.x)) * uv.x;
    float r1 = gv.y / (1.f + __expf(-gv.y)) * uv.y;
    float r2 = gv.z / (1.f + __expf(-gv.z)) * uv.z;
    float r3 = gv.w / (1.f + __expf(-gv.w)) * uv.w;
    ((__half2*)out)[2*i]     = __floats2half2_rn(r0, r1);
    ((__half2*)out)[2*i + 1] = __floats2half2_rn(r2, r3);
}

// ---------------- launch ----------------
extern "C" void kernel_launch(void* const* d_in, const int* in_sizes, int n_in,
                              void* d_out, int out_size) {
    (void)in_sizes; (void)n_in; (void)out_size;
    const float* x      = (const float*)d_in[0];
    const float* w_qkv  = (const float*)d_in[1];
    const float* w_o    = (const float*)d_in[2];
    const float* w_gate = (const float*)d_in[3];
    const float* w_up   = (const float*)d_in[4];
    const float* w_down = (const float*)d_in[5];
    const float* rms1   = (const float*)d_in[6];
    const float* rms2   = (const float*)d_in[7];
    float* out = (float*)d_out;

    __half *h, *qkvh, *vT, *attn, *gateh, *wq, *wo, *wg, *wu, *wd;
    float *x1, *gate, *up;
    cudaGetSymbolAddress((void**)&h,     g_h);
    cudaGetSymbolAddress((void**)&qkvh,  g_qkvh);
    cudaGetSymbolAddress((void**)&vT,    g_vT);
    cudaGetSymbolAddress((void**)&attn,  g_attn);
    cudaGetSymbolAddress((void**)&x1,    g_x1);
    cudaGetSymbolAddress((void**)&gate,  g_gate);
    cudaGetSymbolAddress((void**)&up,    g_up);
    cudaGetSymbolAddress((void**)&gateh, g_gateh);
    cudaGetSymbolAddress((void**)&wq,    g_wqT);
    cudaGetSymbolAddress((void**)&wo,    g_woT);
    cudaGetSymbolAddress((void**)&wg,    g_wgT);
    cudaGetSymbolAddress((void**)&wu,    g_wuT);
    cudaGetSymbolAddress((void**)&wd,    g_wdT);

    cudaFuncSetAttribute(attn_mma_kernel,
                         cudaFuncAttributeMaxDynamicSharedMemorySize, ATTN_SMEM);
    cudaFuncSetAttribute(gemm_mma_kernel<0>,
                         cudaFuncAttributeMaxDynamicSharedMemorySize, GEMM_SMEM);
    cudaFuncSetAttribute(gemm_mma_kernel<1>,
                         cudaFuncAttributeMaxDynamicSharedMemorySize, GEMM_SMEM);
    cudaFuncSetAttribute(gemm_mma_kernel<3>,
                         cudaFuncAttributeMaxDynamicSharedMemorySize, GEMM_SMEM);

    dim3 tb(32, 8);
    convT_kernel<<<dim3((3*H_*HD_)/32, D_/32), tb>>>(w_qkv, wq, D_, 3*H_*HD_);  // 1
    convT_kernel<<<dim3(D_/32, D_/32), tb>>>(w_o, wo, D_, D_);                  // 2
    rmsnorm_kernel<<<NR, 256>>>(x, rms1, h);                                    // 3
    gemm_mma_kernel<3><<<dim3((3*H_*HD_)/128, NR/128), 256, GEMM_SMEM>>>(
        h, wq, nullptr, (float*)qkvh, 3*H_*HD_, D_);                            // 4
    vT_kernel<<<dim3(S_/32, HD_/32, B_*H_), dim3(32, 8)>>>(qkvh, vT);           // 5
    attn_mma_kernel<<<dim3(S_/ABR, H_, B_), 256, ATTN_SMEM>>>(qkvh, vT, attn);  // 6
    gemm_mma_kernel<1><<<dim3(D_/128, NR/128), 256, GEMM_SMEM>>>(
        attn, wo, x, x1, D_, D_);                                               // 7
    rmsnorm_kernel<<<NR, 256>>>(x1, rms2, h);                                   // 8
    convT_kernel<<<dim3(MFF/32, D_/32), tb>>>(w_gate, wg, D_, MFF);             // 9
    convT_kernel<<<dim3(MFF/32, D_/32), tb>>>(w_up,   wu, D_, MFF);             // 10
    convT_kernel<<<dim3(D_/32, MFF/32), tb>>>(w_down, wd, MFF, D_);             // 11
    gemm_mma_kernel<0><<<dim3(MFF/128, NR/128), 256, GEMM_SMEM>>>(
        h, wg, nullptr, gate, MFF, D_);                                         // 12
    gemm_mma_kernel<0><<<dim3(MFF/128, NR/128), 256, GEMM_SMEM>>>(
        h, wu, nullptr, up, MFF, D_);                                           // 13
    silu_mul_kernel<<<(unsigned)((size_t)NR * MFF / 4 / 256), 256>>>(gate, up, gateh); // 14
    gemm_mma_kernel<1><<<dim3(D_/128, NR/128), 256, GEMM_SMEM>>>(
        gateh, wd, x1, out, D_, MFF);                                           // 15
}